// round 2
// baseline (speedup 1.0000x reference)
#include <cuda_runtime.h>
#include <math.h>

// Problem constants
constexpr int NN   = 20000;   // nodes
constexpr int EE   = 320000;  // edges per metapath
constexpr int FF   = 256;     // input feature dim
constexpr int HH   = 8;       // heads
constexpr int DD   = 64;      // dim per head
constexpr int HD   = 512;     // H*D
constexpr int MM   = 2;       // metapaths
constexpr int CC   = 5;       // classes
constexpr int HIDN = 128;     // semantic hidden

// ---------------- device scratch (static globals: allocation-free) ----------
__device__ float g_feat[MM][NN][HD];
__device__ float g_z[MM][NN][HD];
__device__ float g_el[MM][NN][HH];
__device__ float g_er[MM][NN][HH];
__device__ int   g_deg[MM][NN];
__device__ int   g_rowptr[MM][NN + 1];
__device__ int   g_cur[MM][NN];
__device__ int   g_csr_src[MM][EE];
__device__ float g_w[MM * NN];
__device__ float g_wsum[MM];
__device__ float g_beta[MM];

// ---------------- 1) feat = h @ W[mp]  (20000x256 @ 256x512) ----------------
// BM=128, BN=64, BK=16, 256 threads, 8x4 micro-tile
__global__ void feat_gemm_kernel(const float* __restrict__ h,
                                 const float* __restrict__ Wall) {
    const int mp = blockIdx.z;
    const float* W = Wall + mp * FF * HD;
    const int rowBase = blockIdx.x * 128;
    const int colBase = blockIdx.y * 64;

    __shared__ float As[16][128];
    __shared__ float Bs[16][64];

    const int t  = threadIdx.x;          // 0..255
    const int tr = t / 16, tc = t % 16;
    const int r0 = tr * 8, c0 = tc * 4;

    float acc[8][4];
#pragma unroll
    for (int i = 0; i < 8; i++)
#pragma unroll
        for (int j = 0; j < 4; j++) acc[i][j] = 0.f;

    for (int k0 = 0; k0 < FF; k0 += 16) {
        // load A tile: 128x16 floats = 512 float4, 2 per thread
#pragma unroll
        for (int j = 0; j < 2; j++) {
            int idx = t + 256 * j;       // 0..511
            int row = idx >> 2;          // 0..127
            int kq  = idx & 3;           // 0..3
            int grow = rowBase + row;
            float4 v = (grow < NN)
                ? *(const float4*)&h[grow * FF + k0 + kq * 4]
                : make_float4(0.f, 0.f, 0.f, 0.f);
            As[kq * 4 + 0][row] = v.x;
            As[kq * 4 + 1][row] = v.y;
            As[kq * 4 + 2][row] = v.z;
            As[kq * 4 + 3][row] = v.w;
        }
        // load B tile: 16x64 = 256 float4, 1 per thread
        {
            int k = t >> 4, nq = t & 15;
            float4 v = *(const float4*)&W[(k0 + k) * HD + colBase + nq * 4];
            *(float4*)&Bs[k][nq * 4] = v;
        }
        __syncthreads();

#pragma unroll
        for (int k = 0; k < 16; k++) {
            float a[8], b[4];
#pragma unroll
            for (int i = 0; i < 8; i++) a[i] = As[k][r0 + i];
#pragma unroll
            for (int j = 0; j < 4; j++) b[j] = Bs[k][c0 + j];
#pragma unroll
            for (int i = 0; i < 8; i++)
#pragma unroll
                for (int j = 0; j < 4; j++) acc[i][j] += a[i] * b[j];
        }
        __syncthreads();
    }

#pragma unroll
    for (int i = 0; i < 8; i++) {
        int grow = rowBase + r0 + i;
        if (grow < NN) {
            float4 v = make_float4(acc[i][0], acc[i][1], acc[i][2], acc[i][3]);
            *(float4*)&g_feat[mp][grow][colBase + c0] = v;
        }
    }
}

// ---------------- 2) el/er per (mp, n, h) -----------------------------------
__global__ void elr_kernel(const float* __restrict__ al,
                           const float* __restrict__ ar) {
    int gid = blockIdx.x * blockDim.x + threadIdx.x;
    if (gid >= MM * NN * HH) return;
    int mp  = gid / (NN * HH);
    int rem = gid % (NN * HH);
    int n = rem / HH, hh = rem % HH;
    const float* f = &g_feat[mp][n][hh * DD];
    const float* a = al + mp * HD + hh * DD;
    const float* b = ar + mp * HD + hh * DD;
    float sl = 0.f, sr = 0.f;
#pragma unroll 8
    for (int d = 0; d < DD; d++) {
        float fv = f[d];
        sl += fv * a[d];
        sr += fv * b[d];
    }
    g_el[mp][n][hh] = sl;
    g_er[mp][n][hh] = sr;
}

// ---------------- 3) CSR build ----------------------------------------------
__global__ void count_kernel(const int* __restrict__ dst) {
    int mp = blockIdx.y;
    int e = blockIdx.x * blockDim.x + threadIdx.x;
    if (e < EE) atomicAdd(&g_deg[mp][dst[mp * EE + e]], 1);
}

__global__ void scan_kernel() {
    const int mp = blockIdx.x;
    const int NT = 512;
    __shared__ int wsum[16];
    int t = threadIdx.x, lane = t & 31, wid = t >> 5;
    int carry = 0;
    for (int base = 0; base < NN; base += NT) {
        int i = base + t;
        int v = (i < NN) ? g_deg[mp][i] : 0;
        int x = v;
#pragma unroll
        for (int off = 1; off < 32; off <<= 1) {
            int y = __shfl_up_sync(0xffffffffu, x, off);
            if (lane >= off) x += y;
        }
        if (lane == 31) wsum[wid] = x;
        __syncthreads();
        if (wid == 0) {
            int s = (lane < 16) ? wsum[lane] : 0;
#pragma unroll
            for (int off = 1; off < 16; off <<= 1) {
                int y = __shfl_up_sync(0xffffffffu, s, off);
                if (lane >= off) s += y;
            }
            if (lane < 16) wsum[lane] = s;
        }
        __syncthreads();
        int woff = wid ? wsum[wid - 1] : 0;
        int excl = carry + woff + x - v;
        if (i < NN) {
            g_rowptr[mp][i] = excl;
            g_cur[mp][i]    = excl;
        }
        carry += wsum[15];
        __syncthreads();
    }
    if (t == 0) g_rowptr[mp][NN] = carry;
}

__global__ void scatter_kernel(const int* __restrict__ src,
                               const int* __restrict__ dst) {
    int mp = blockIdx.y;
    int e = blockIdx.x * blockDim.x + threadIdx.x;
    if (e < EE) {
        int d = dst[mp * EE + e];
        int pos = atomicAdd(&g_cur[mp][d], 1);
        g_csr_src[mp][pos] = src[mp * EE + e];
    }
}

// ---------------- 4) edge softmax + aggregation (block per dst node) --------
__global__ void agg_kernel(const float* __restrict__ bias) {
    const int v  = blockIdx.x;
    const int mp = blockIdx.y;
    const int t  = threadIdx.x;  // 128 threads

    __shared__ float ser[HH], smax[HH], sden[HH];
    __shared__ float sex[16][HH];
    __shared__ int   ssrc[16];

    const int start = g_rowptr[mp][v];
    const int deg   = g_rowptr[mp][v + 1] - start;

    if (t < HH) {
        ser[t]  = g_er[mp][v][t];
        sden[t] = 0.f;
    }
    __syncthreads();

    // pass 1 (warp 0): per-head max of leaky_relu(el[src]+er[v])
    if (t < 32) {
        int hh = t & 7;
        float erh = ser[hh];
        float lm = -1e30f;
        for (int i = t >> 3; i < deg; i += 4) {
            int s = g_csr_src[mp][start + i];
            float e = g_el[mp][s][hh] + erh;
            e = (e > 0.f) ? e : 0.2f * e;
            lm = fmaxf(lm, e);
        }
        lm = fmaxf(lm, __shfl_xor_sync(0xffffffffu, lm, 8));
        lm = fmaxf(lm, __shfl_xor_sync(0xffffffffu, lm, 16));
        if (t < 8) smax[t] = lm;
    }
    __syncthreads();

    // pass 2: chunked exp + weighted accumulation
    float acc0 = 0.f, acc1 = 0.f, acc2 = 0.f, acc3 = 0.f;
    const int d0  = t * 4;      // contiguous float4 per thread
    const int myh = t >> 4;     // head owning these 4 dims

    for (int base = 0; base < deg; base += 16) {
        int cn = min(16, deg - base);
        if (t < cn * 8) {
            int i = t >> 3, hh = t & 7;
            int s = g_csr_src[mp][start + base + i];
            if (hh == 0) ssrc[i] = s;
            float e = g_el[mp][s][hh] + ser[hh];
            e = (e > 0.f) ? e : 0.2f * e;
            sex[i][hh] = expf(e - smax[hh]);
        }
        __syncthreads();
        if (t < 8) {
            float dsum = 0.f;
            for (int i = 0; i < cn; i++) dsum += sex[i][t];
            sden[t] += dsum;
        }
        for (int i = 0; i < cn; i++) {
            int s = ssrc[i];
            float w = sex[i][myh];
            float4 fv = *(const float4*)&g_feat[mp][s][d0];
            acc0 += w * fv.x;
            acc1 += w * fv.y;
            acc2 += w * fv.z;
            acc3 += w * fv.w;
        }
        __syncthreads();
    }

    float inv = 1.f / fmaxf(sden[myh], 1e-9f);
    const float* b = bias + mp * HD + d0;
    float o0 = acc0 * inv + b[0];
    float o1 = acc1 * inv + b[1];
    float o2 = acc2 * inv + b[2];
    float o3 = acc3 * inv + b[3];
    o0 = (o0 > 0.f) ? o0 : (expf(o0) - 1.f);
    o1 = (o1 > 0.f) ? o1 : (expf(o1) - 1.f);
    o2 = (o2 > 0.f) ? o2 : (expf(o2) - 1.f);
    o3 = (o3 > 0.f) ? o3 : (expf(o3) - 1.f);
    *(float4*)&g_z[mp][v][d0] = make_float4(o0, o1, o2, o3);
}

// ---------------- 5) semantic attention GEMM + fused epilogue ---------------
// rows = M*N = 40000 (exactly 625 * 64), K = 512, cols = 128 (one block-wide)
__global__ void sem_kernel(const float* __restrict__ W1,
                           const float* __restrict__ b1,
                           const float* __restrict__ W2) {
    const int rowBase = blockIdx.x * 64;
    __shared__ float As[16][64];
    __shared__ float Bs[16][128];
    __shared__ float sred[64];

    const int t  = threadIdx.x;  // 256
    const int tr = t / 16, tc = t % 16;
    const int r0 = tr * 4, c0 = tc * 8;

    float acc[4][8];
#pragma unroll
    for (int i = 0; i < 4; i++)
#pragma unroll
        for (int j = 0; j < 8; j++) acc[i][j] = 0.f;

    const float* Z = &g_z[0][0][0];  // viewed as [40000][512]

    for (int k0 = 0; k0 < HD; k0 += 16) {
        // A tile: 64x16 = 256 float4, 1 per thread
        {
            int row = t >> 2, kq = t & 3;
            float4 v = *(const float4*)&Z[(rowBase + row) * HD + k0 + kq * 4];
            As[kq * 4 + 0][row] = v.x;
            As[kq * 4 + 1][row] = v.y;
            As[kq * 4 + 2][row] = v.z;
            As[kq * 4 + 3][row] = v.w;
        }
        // B tile: 16x128 = 512 float4, 2 per thread
#pragma unroll
        for (int j = 0; j < 2; j++) {
            int idx = t + 256 * j;
            int k = idx >> 5, nq = idx & 31;
            *(float4*)&Bs[k][nq * 4] =
                *(const float4*)&W1[(k0 + k) * HIDN + nq * 4];
        }
        __syncthreads();
#pragma unroll
        for (int k = 0; k < 16; k++) {
            float a[4], b[8];
#pragma unroll
            for (int i = 0; i < 4; i++) a[i] = As[k][r0 + i];
#pragma unroll
            for (int j = 0; j < 8; j++) b[j] = Bs[k][c0 + j];
#pragma unroll
            for (int i = 0; i < 4; i++)
#pragma unroll
                for (int j = 0; j < 8; j++) acc[i][j] += a[i] * b[j];
        }
        __syncthreads();
    }

    // epilogue: w[row] = sum_j tanh(acc + b1[j]) * W2[j]
    if (t < 64) sred[t] = 0.f;
    __syncthreads();
    float rsum[4] = {0.f, 0.f, 0.f, 0.f};
#pragma unroll
    for (int j = 0; j < 8; j++) {
        float w2 = W2[c0 + j];
        float bb = b1[c0 + j];
#pragma unroll
        for (int i = 0; i < 4; i++)
            rsum[i] += tanhf(acc[i][j] + bb) * w2;
    }
#pragma unroll
    for (int i = 0; i < 4; i++) atomicAdd(&sred[r0 + i], rsum[i]);
    __syncthreads();
    if (t < 64) g_w[rowBase + t] = sred[t];
}

// ---------------- 6) reduce w -> wsum, then beta ----------------------------
__global__ void wsum_kernel() {
    __shared__ float sp[MM];
    if (threadIdx.x < MM) sp[threadIdx.x] = 0.f;
    __syncthreads();
    int i = blockIdx.x * blockDim.x + threadIdx.x;
    if (i < MM * NN) atomicAdd(&sp[i / NN], g_w[i]);
    __syncthreads();
    if (threadIdx.x < MM) atomicAdd(&g_wsum[threadIdx.x], sp[threadIdx.x]);
}

__global__ void beta_kernel() {
    float a = g_wsum[0] / (float)NN;
    float b = g_wsum[1] / (float)NN;
    float m = fmaxf(a, b);
    float ea = expf(a - m), eb = expf(b - m);
    float s = ea + eb;
    g_beta[0] = ea / s;
    g_beta[1] = eb / s;
}

// ---------------- 7) prediction: out = (beta0*z0+beta1*z1) @ pred_W + b -----
__global__ void pred_kernel(const float* __restrict__ pw,
                            const float* __restrict__ pb,
                            float* __restrict__ out) {
    int gwarp = (blockIdx.x * blockDim.x + threadIdx.x) >> 5;
    int lane  = threadIdx.x & 31;
    if (gwarp >= NN) return;
    float b0 = g_beta[0], b1 = g_beta[1];
    float acc[CC];
#pragma unroll
    for (int c = 0; c < CC; c++) acc[c] = 0.f;
    const float* z0 = g_z[0][gwarp];
    const float* z1 = g_z[1][gwarp];
    for (int d = lane; d < HD; d += 32) {
        float hv = b0 * z0[d] + b1 * z1[d];
#pragma unroll
        for (int c = 0; c < CC; c++) acc[c] += hv * __ldg(&pw[d * CC + c]);
    }
#pragma unroll
    for (int off = 16; off; off >>= 1)
#pragma unroll
        for (int c = 0; c < CC; c++)
            acc[c] += __shfl_xor_sync(0xffffffffu, acc[c], off);
    if (lane == 0) {
#pragma unroll
        for (int c = 0; c < CC; c++) out[gwarp * CC + c] = acc[c] + pb[c];
    }
}

// ---------------- launch ----------------------------------------------------
extern "C" void kernel_launch(void* const* d_in, const int* in_sizes, int n_in,
                              void* d_out, int out_size) {
    const float* h      = (const float*)d_in[0];
    const int*   src    = (const int*)d_in[1];
    const int*   dst    = (const int*)d_in[2];
    const float* W      = (const float*)d_in[3];
    const float* attn_l = (const float*)d_in[4];
    const float* attn_r = (const float*)d_in[5];
    const float* bias_g = (const float*)d_in[6];
    const float* sem_W1 = (const float*)d_in[7];
    const float* sem_b1 = (const float*)d_in[8];
    const float* sem_W2 = (const float*)d_in[9];
    const float* pred_W = (const float*)d_in[10];
    const float* pred_b = (const float*)d_in[11];
    float* out = (float*)d_out;

    void* p_deg = nullptr;
    void* p_ws  = nullptr;
    cudaGetSymbolAddress(&p_deg, g_deg);
    cudaGetSymbolAddress(&p_ws, g_wsum);
    cudaMemsetAsync(p_deg, 0, sizeof(int) * MM * NN, 0);
    cudaMemsetAsync(p_ws, 0, sizeof(float) * MM, 0);

    // 1) feat = h @ W
    {
        dim3 grid((NN + 127) / 128, HD / 64, MM);
        feat_gemm_kernel<<<grid, 256>>>(h, W);
    }
    // 2) el/er
    {
        int total = MM * NN * HH;
        elr_kernel<<<(total + 255) / 256, 256>>>(attn_l, attn_r);
    }
    // 3) CSR
    {
        dim3 grid((EE + 255) / 256, MM);
        count_kernel<<<grid, 256>>>(dst);
        scan_kernel<<<MM, 512>>>();
        scatter_kernel<<<grid, 256>>>(src, dst);
    }
    // 4) edge softmax + aggregate
    {
        dim3 grid(NN, MM);
        agg_kernel<<<grid, 128>>>(bias_g);
    }
    // 5) semantic attention scores
    sem_kernel<<<(MM * NN) / 64, 256>>>(sem_W1, sem_b1, sem_W2);
    // 6) beta
    wsum_kernel<<<(MM * NN + 255) / 256, 256>>>();
    beta_kernel<<<1, 1>>>();
    // 7) prediction
    pred_kernel<<<(NN * 32 + 255) / 256, 256>>>(pred_W, pred_b, out);
}

// round 5
// speedup vs baseline: 1.4719x; 1.4719x over previous
#include <cuda_runtime.h>
#include <cuda_bf16.h>
#include <cstdint>
#include <math.h>

// Problem constants
constexpr int NN   = 20000;
constexpr int EE   = 320000;
constexpr int FF   = 256;
constexpr int HH   = 8;
constexpr int DD   = 64;
constexpr int HD   = 512;
constexpr int MM   = 2;
constexpr int CC   = 5;
constexpr int HIDN = 128;
constexpr int NB   = 80;       // scan blocks
constexpr int KK3  = 3 * FF;   // 768: [hi | hi | lo] x [hi | lo | hi]

// ---------------- device scratch ----------------
__device__ float g_feat[MM][NN][HD];
__device__ float g_z[MM][NN][HD];
__device__ float g_el[MM][NN][HH];
__device__ float g_er[MM][NN][HH];
__device__ int   g_deg[MM][NN];
__device__ int   g_rowptr[MM][NN + 1];
__device__ int   g_cur[MM][NN];
__device__ int   g_csr_src[MM][EE];
__device__ float g_w[MM * NN];
__device__ float g_wsum[MM];
__device__ float g_beta[MM];
__device__ int   g_psum[MM][NB];
__device__ int   g_boff[MM][NB];
__device__ __nv_bfloat16 g_A[NN][KK3];        // h split:  [hi(256) | hi(256) | lo(256)]
__device__ __nv_bfloat16 g_B[MM][HD][KK3];    // Wt split: [hi(256) | lo(256) | hi(256)]

// ---------------- conversion kernels ----------------
__device__ __forceinline__ uint32_t pack_bf2(float x, float y) {
    __nv_bfloat162 p = __floats2bfloat162_rn(x, y);
    return *(uint32_t*)&p;
}

__global__ void conv_h_kernel(const float* __restrict__ h) {
    int idx = blockIdx.x * blockDim.x + threadIdx.x;   // one per 4 floats
    if (idx >= NN * FF / 4) return;
    int row = idx >> 6;
    int kk  = (idx & 63) * 4;
    float4 v = *(const float4*)&h[row * FF + kk];
    float hx = __bfloat162float(__float2bfloat16(v.x));
    float hy = __bfloat162float(__float2bfloat16(v.y));
    float hz = __bfloat162float(__float2bfloat16(v.z));
    float hw = __bfloat162float(__float2bfloat16(v.w));
    uint2 hi = make_uint2(pack_bf2(v.x, v.y), pack_bf2(v.z, v.w));
    uint2 lo = make_uint2(pack_bf2(v.x - hx, v.y - hy), pack_bf2(v.z - hz, v.w - hw));
    *(uint2*)&g_A[row][kk]           = hi;
    *(uint2*)&g_A[row][kk + FF]      = hi;
    *(uint2*)&g_A[row][kk + 2 * FF]  = lo;
}

__global__ void conv_w_kernel(const float* __restrict__ W) {
    __shared__ float tile[32][33];
    int mp = blockIdx.z;
    int n0 = blockIdx.x * 32, k0 = blockIdx.y * 32;
    int tx = threadIdx.x, ty = threadIdx.y;  // 32 x 8
#pragma unroll
    for (int j = 0; j < 4; j++)
        tile[ty + j * 8][tx] = W[mp * FF * HD + (k0 + ty + j * 8) * HD + n0 + tx];
    __syncthreads();
#pragma unroll
    for (int j = 0; j < 4; j++) {
        int n = n0 + ty + j * 8, k = k0 + tx;
        float x = tile[tx][ty + j * 8];
        __nv_bfloat16 hi = __float2bfloat16(x);
        __nv_bfloat16 lo = __float2bfloat16(x - __bfloat162float(hi));
        g_B[mp][n][k]          = hi;
        g_B[mp][n][k + FF]     = lo;
        g_B[mp][n][k + 2 * FF] = hi;
    }
}

// ---------------- feat GEMM via mma.sync bf16 (fused el/er epilogue) --------
// Block: 128 rows x 64 cols (one head). 8 warps = 4(m) x 2(n) of 32x32 tiles.
// K = 768 in 12 chunks of 64.
__global__ void __launch_bounds__(256, 3)
feat_mma_kernel(const float* __restrict__ al, const float* __restrict__ ar) {
    __shared__ __nv_bfloat16 As[128][72];   // stride 72: conflict-free frags
    __shared__ __nv_bfloat16 Bs[64][72];
    __shared__ float s_al[64], s_ar[64], s_el[128], s_er[128];

    const int t = threadIdx.x, lane = t & 31, wid = t >> 5;
    const int wm = wid & 3, wn = wid >> 2;
    const int rowBase = blockIdx.x * 128;
    const int head    = blockIdx.y;
    const int mp      = blockIdx.z;
    const int colBase = head * DD;

    if (t < 64) {
        s_al[t] = al[mp * HD + colBase + t];
        s_ar[t] = ar[mp * HD + colBase + t];
    }
    if (t < 128) { s_el[t] = 0.f; s_er[t] = 0.f; }

    float d[2][4][4] = {};

    for (int kc = 0; kc < 12; kc++) {
        // A chunk: 128x64 = 1024 uint4, 4 per thread
#pragma unroll
        for (int j = 0; j < 4; j++) {
            int idx = t + j * 256;
            int row = idx >> 3, kq = (idx & 7) * 8;
            int grow = rowBase + row;
            uint4 v = make_uint4(0, 0, 0, 0);
            if (grow < NN) v = *(const uint4*)&g_A[grow][kc * 64 + kq];
            *(uint4*)&As[row][kq] = v;
        }
        // B chunk: 64x64 = 512 uint4, 2 per thread
#pragma unroll
        for (int j = 0; j < 2; j++) {
            int idx = t + j * 256;
            int row = idx >> 3, kq = (idx & 7) * 8;
            *(uint4*)&Bs[row][kq] = *(const uint4*)&g_B[mp][colBase + row][kc * 64 + kq];
        }
        __syncthreads();

#pragma unroll
        for (int ks = 0; ks < 4; ks++) {
            const int kk = ks * 16 + (lane & 3) * 2;
            uint32_t afr[2][4], bfr[4][2];
#pragma unroll
            for (int mi = 0; mi < 2; mi++) {
                int r = wm * 32 + mi * 16 + (lane >> 2);
                afr[mi][0] = *(const uint32_t*)&As[r][kk];
                afr[mi][1] = *(const uint32_t*)&As[r + 8][kk];
                afr[mi][2] = *(const uint32_t*)&As[r][kk + 8];
                afr[mi][3] = *(const uint32_t*)&As[r + 8][kk + 8];
            }
#pragma unroll
            for (int ni = 0; ni < 4; ni++) {
                int n = wn * 32 + ni * 8 + (lane >> 2);
                bfr[ni][0] = *(const uint32_t*)&Bs[n][kk];
                bfr[ni][1] = *(const uint32_t*)&Bs[n][kk + 8];
            }
#pragma unroll
            for (int mi = 0; mi < 2; mi++)
#pragma unroll
                for (int ni = 0; ni < 4; ni++)
                    asm volatile(
                        "mma.sync.aligned.m16n8k16.row.col.f32.bf16.bf16.f32 "
                        "{%0,%1,%2,%3}, {%4,%5,%6,%7}, {%8,%9}, {%0,%1,%2,%3};"
                        : "+f"(d[mi][ni][0]), "+f"(d[mi][ni][1]),
                          "+f"(d[mi][ni][2]), "+f"(d[mi][ni][3])
                        : "r"(afr[mi][0]), "r"(afr[mi][1]),
                          "r"(afr[mi][2]), "r"(afr[mi][3]),
                          "r"(bfr[ni][0]), "r"(bfr[ni][1]));
        }
        __syncthreads();
    }

    // ---- epilogue: write feat, reduce el/er ----
    const int c0base = wn * 32 + (lane & 3) * 2;
#pragma unroll
    for (int mi = 0; mi < 2; mi++) {
#pragma unroll
        for (int half = 0; half < 2; half++) {
            int r = wm * 32 + mi * 16 + half * 8 + (lane >> 2);
            int grow = rowBase + r;
            float el = 0.f, er = 0.f;
#pragma unroll
            for (int ni = 0; ni < 4; ni++) {
                float v0 = d[mi][ni][half * 2 + 0];
                float v1 = d[mi][ni][half * 2 + 1];
                int c = c0base + ni * 8;
                el += v0 * s_al[c] + v1 * s_al[c + 1];
                er += v0 * s_ar[c] + v1 * s_ar[c + 1];
                if (grow < NN)
                    *(float2*)&g_feat[mp][grow][colBase + c] = make_float2(v0, v1);
            }
            el += __shfl_xor_sync(0xffffffffu, el, 1);
            el += __shfl_xor_sync(0xffffffffu, el, 2);
            er += __shfl_xor_sync(0xffffffffu, er, 1);
            er += __shfl_xor_sync(0xffffffffu, er, 2);
            if ((lane & 3) == 0) {
                atomicAdd(&s_el[r], el);
                atomicAdd(&s_er[r], er);
            }
        }
    }
    __syncthreads();
    if (t < 128) {
        int grow = rowBase + t;
        if (grow < NN) {
            g_el[mp][grow][head] = s_el[t];
            g_er[mp][grow][head] = s_er[t];
        }
    }
}

// ---------------- CSR build ----------------
__global__ void count_kernel(const int* __restrict__ dst) {
    int mp = blockIdx.y;
    int e = blockIdx.x * blockDim.x + threadIdx.x;
    if (e < EE) atomicAdd(&g_deg[mp][dst[mp * EE + e]], 1);
}

__global__ void scan_partial() {  // grid (NB, MM), 256 thr
    int mp = blockIdx.y;
    int i = blockIdx.x * 256 + threadIdx.x;
    int v = (i < NN) ? g_deg[mp][i] : 0;
#pragma unroll
    for (int off = 16; off; off >>= 1) v += __shfl_xor_sync(0xffffffffu, v, off);
    __shared__ int ws[8];
    if ((threadIdx.x & 31) == 0) ws[threadIdx.x >> 5] = v;
    __syncthreads();
    if (threadIdx.x == 0) {
        int s = 0;
#pragma unroll
        for (int w = 0; w < 8; w++) s += ws[w];
        g_psum[mp][blockIdx.x] = s;
    }
}

__global__ void scan_mid() {  // grid (MM), 128 thr
    int mp = blockIdx.x;
    int t = threadIdx.x, lane = t & 31, wid = t >> 5;
    int v = (t < NB) ? g_psum[mp][t] : 0;
    int x = v;
#pragma unroll
    for (int off = 1; off < 32; off <<= 1) {
        int y = __shfl_up_sync(0xffffffffu, x, off);
        if (lane >= off) x += y;
    }
    __shared__ int ws[4];
    if (lane == 31) ws[wid] = x;
    __syncthreads();
    int woff = 0;
    for (int w = 0; w < wid; w++) woff += ws[w];
    if (t < NB) g_boff[mp][t] = woff + x - v;
}

__global__ void scan_final() {  // grid (NB, MM), 256 thr
    int mp = blockIdx.y;
    int t = threadIdx.x, lane = t & 31, wid = t >> 5;
    int i = blockIdx.x * 256 + t;
    int v = (i < NN) ? g_deg[mp][i] : 0;
    int x = v;
#pragma unroll
    for (int off = 1; off < 32; off <<= 1) {
        int y = __shfl_up_sync(0xffffffffu, x, off);
        if (lane >= off) x += y;
    }
    __shared__ int ws[8];
    if (lane == 31) ws[wid] = x;
    __syncthreads();
    int woff = 0;
    for (int w = 0; w < wid; w++) woff += ws[w];
    int excl = g_boff[mp][blockIdx.x] + woff + x - v;
    if (i < NN) {
        g_rowptr[mp][i] = excl;
        g_cur[mp][i]    = excl;
        if (i == NN - 1) g_rowptr[mp][NN] = excl + v;
    }
}

__global__ void scatter_kernel(const int* __restrict__ src,
                               const int* __restrict__ dst) {
    int mp = blockIdx.y;
    int e = blockIdx.x * blockDim.x + threadIdx.x;
    if (e < EE) {
        int d = dst[mp * EE + e];
        int pos = atomicAdd(&g_cur[mp][d], 1);
        g_csr_src[mp][pos] = src[mp * EE + e];
    }
}

// ---------------- edge softmax + aggregation (single pass, no max) ---------
__global__ void agg_kernel(const float* __restrict__ bias) {
    const int v  = blockIdx.x;
    const int mp = blockIdx.y;
    const int t  = threadIdx.x;  // 128

    __shared__ float ser[HH], sden[HH];
    __shared__ float sex[16][HH];
    __shared__ int   ssrc[16];

    const int start = g_rowptr[mp][v];
    const int deg   = g_rowptr[mp][v + 1] - start;

    if (t < HH) {
        ser[t]  = g_er[mp][v][t];
        sden[t] = 0.f;
    }
    __syncthreads();

    float acc0 = 0.f, acc1 = 0.f, acc2 = 0.f, acc3 = 0.f;
    const int d0  = t * 4;
    const int myh = t >> 4;

    for (int base = 0; base < deg; base += 16) {
        int cn = min(16, deg - base);
        if (t < cn * 8) {
            int i = t >> 3, hh = t & 7;
            int s = g_csr_src[mp][start + base + i];
            if (hh == 0) ssrc[i] = s;
            float e = g_el[mp][s][hh] + ser[hh];
            e = (e > 0.f) ? e : 0.2f * e;
            sex[i][hh] = expf(e);
        }
        __syncthreads();
        if (t < 8) {
            float dsum = 0.f;
            for (int i = 0; i < cn; i++) dsum += sex[i][t];
            sden[t] += dsum;
        }
        for (int i = 0; i < cn; i++) {
            int s = ssrc[i];
            float w = sex[i][myh];
            float4 fv = *(const float4*)&g_feat[mp][s][d0];
            acc0 += w * fv.x;
            acc1 += w * fv.y;
            acc2 += w * fv.z;
            acc3 += w * fv.w;
        }
        __syncthreads();
    }

    float inv = 1.f / fmaxf(sden[myh], 1e-9f);
    const float* b = bias + mp * HD + d0;
    float o0 = acc0 * inv + b[0];
    float o1 = acc1 * inv + b[1];
    float o2 = acc2 * inv + b[2];
    float o3 = acc3 * inv + b[3];
    o0 = (o0 > 0.f) ? o0 : (expf(o0) - 1.f);
    o1 = (o1 > 0.f) ? o1 : (expf(o1) - 1.f);
    o2 = (o2 > 0.f) ? o2 : (expf(o2) - 1.f);
    o3 = (o3 > 0.f) ? o3 : (expf(o3) - 1.f);
    *(float4*)&g_z[mp][v][d0] = make_float4(o0, o1, o2, o3);
}

// ---------------- semantic attention GEMM + fused epilogue ----------------
__global__ void sem_kernel(const float* __restrict__ W1,
                           const float* __restrict__ b1,
                           const float* __restrict__ W2) {
    const int rowBase = blockIdx.x * 64;
    __shared__ float As[16][64];
    __shared__ float Bs[16][128];
    __shared__ float sred[64];

    const int t  = threadIdx.x;  // 256
    const int tr = t / 16, tc = t % 16;
    const int r0 = tr * 4, c0 = tc * 8;

    float acc[4][8];
#pragma unroll
    for (int i = 0; i < 4; i++)
#pragma unroll
        for (int j = 0; j < 8; j++) acc[i][j] = 0.f;

    const float* Z = &g_z[0][0][0];

    for (int k0 = 0; k0 < HD; k0 += 16) {
        {
            int row = t >> 2, kq = t & 3;
            float4 v = *(const float4*)&Z[(rowBase + row) * HD + k0 + kq * 4];
            As[kq * 4 + 0][row] = v.x;
            As[kq * 4 + 1][row] = v.y;
            As[kq * 4 + 2][row] = v.z;
            As[kq * 4 + 3][row] = v.w;
        }
#pragma unroll
        for (int j = 0; j < 2; j++) {
            int idx = t + 256 * j;
            int k = idx >> 5, nq = idx & 31;
            *(float4*)&Bs[k][nq * 4] = *(const float4*)&W1[(k0 + k) * HIDN + nq * 4];
        }
        __syncthreads();
#pragma unroll
        for (int k = 0; k < 16; k++) {
            float a[4], b[8];
#pragma unroll
            for (int i = 0; i < 4; i++) a[i] = As[k][r0 + i];
#pragma unroll
            for (int j = 0; j < 8; j++) b[j] = Bs[k][c0 + j];
#pragma unroll
            for (int i = 0; i < 4; i++)
#pragma unroll
                for (int j = 0; j < 8; j++) acc[i][j] += a[i] * b[j];
        }
        __syncthreads();
    }

    if (t < 64) sred[t] = 0.f;
    __syncthreads();
    float rsum[4] = {0.f, 0.f, 0.f, 0.f};
#pragma unroll
    for (int j = 0; j < 8; j++) {
        float w2 = W2[c0 + j];
        float bb = b1[c0 + j];
#pragma unroll
        for (int i = 0; i < 4; i++)
            rsum[i] += tanhf(acc[i][j] + bb) * w2;
    }
#pragma unroll
    for (int i = 0; i < 4; i++) atomicAdd(&sred[r0 + i], rsum[i]);
    __syncthreads();
    if (t < 64) g_w[rowBase + t] = sred[t];
}

__global__ void wsum_kernel() {
    __shared__ float sp[MM];
    if (threadIdx.x < MM) sp[threadIdx.x] = 0.f;
    __syncthreads();
    int i = blockIdx.x * blockDim.x + threadIdx.x;
    if (i < MM * NN) atomicAdd(&sp[i / NN], g_w[i]);
    __syncthreads();
    if (threadIdx.x < MM) atomicAdd(&g_wsum[threadIdx.x], sp[threadIdx.x]);
}

__global__ void beta_kernel() {
    float a = g_wsum[0] / (float)NN;
    float b = g_wsum[1] / (float)NN;
    float m = fmaxf(a, b);
    float ea = expf(a - m), eb = expf(b - m);
    float s = ea + eb;
    g_beta[0] = ea / s;
    g_beta[1] = eb / s;
}

__global__ void pred_kernel(const float* __restrict__ pw,
                            const float* __restrict__ pb,
                            float* __restrict__ out) {
    int gwarp = (blockIdx.x * blockDim.x + threadIdx.x) >> 5;
    int lane  = threadIdx.x & 31;
    if (gwarp >= NN) return;
    float b0 = g_beta[0], b1 = g_beta[1];
    float acc[CC];
#pragma unroll
    for (int c = 0; c < CC; c++) acc[c] = 0.f;
    const float* z0 = g_z[0][gwarp];
    const float* z1 = g_z[1][gwarp];
    for (int d = lane; d < HD; d += 32) {
        float hv = b0 * z0[d] + b1 * z1[d];
#pragma unroll
        for (int c = 0; c < CC; c++) acc[c] += hv * __ldg(&pw[d * CC + c]);
    }
#pragma unroll
    for (int off = 16; off; off >>= 1)
#pragma unroll
        for (int c = 0; c < CC; c++)
            acc[c] += __shfl_xor_sync(0xffffffffu, acc[c], off);
    if (lane == 0) {
#pragma unroll
        for (int c = 0; c < CC; c++) out[gwarp * CC + c] = acc[c] + pb[c];
    }
}

// ---------------- launch ----------------
extern "C" void kernel_launch(void* const* d_in, const int* in_sizes, int n_in,
                              void* d_out, int out_size) {
    const float* h      = (const float*)d_in[0];
    const int*   src    = (const int*)d_in[1];
    const int*   dst    = (const int*)d_in[2];
    const float* W      = (const float*)d_in[3];
    const float* attn_l = (const float*)d_in[4];
    const float* attn_r = (const float*)d_in[5];
    const float* bias_g = (const float*)d_in[6];
    const float* sem_W1 = (const float*)d_in[7];
    const float* sem_b1 = (const float*)d_in[8];
    const float* sem_W2 = (const float*)d_in[9];
    const float* pred_W = (const float*)d_in[10];
    const float* pred_b = (const float*)d_in[11];
    float* out = (float*)d_out;

    void* p_deg = nullptr;
    void* p_ws  = nullptr;
    cudaGetSymbolAddress(&p_deg, g_deg);
    cudaGetSymbolAddress(&p_ws, g_wsum);
    cudaMemsetAsync(p_deg, 0, sizeof(int) * MM * NN, 0);       // launch 1
    cudaMemsetAsync(p_ws, 0, sizeof(float) * MM, 0);           // launch 2

    conv_h_kernel<<<(NN * FF / 4 + 255) / 256, 256>>>(h);      // launch 3
    {
        dim3 grid(HD / 32, FF / 32, MM);
        conv_w_kernel<<<grid, dim3(32, 8)>>>(W);               // launch 4
    }
    {
        dim3 grid((EE + 255) / 256, MM);
        count_kernel<<<grid, 256>>>(dst);                      // launch 5
    }
    {
        dim3 grid((NN + 127) / 128, HH, MM);
        feat_mma_kernel<<<grid, 256>>>(attn_l, attn_r);        // launch 6 (profiled)
    }
    scan_partial<<<dim3(NB, MM), 256>>>();
    scan_mid<<<MM, 128>>>();
    scan_final<<<dim3(NB, MM), 256>>>();
    {
        dim3 grid((EE + 255) / 256, MM);
        scatter_kernel<<<grid, 256>>>(src, dst);
    }
    {
        dim3 grid(NN, MM);
        agg_kernel<<<grid, 128>>>(bias_g);
    }
    sem_kernel<<<(MM * NN) / 64, 256>>>(sem_W1, sem_b1, sem_W2);
    wsum_kernel<<<(MM * NN + 255) / 256, 256>>>();
    beta_kernel<<<1, 1>>>();
    pred_kernel<<<(NN * 32 + 255) / 256, 256>>>(pred_W, pred_b, out);
}

// round 6
// speedup vs baseline: 2.1117x; 1.4347x over previous
#include <cuda_runtime.h>
#include <cuda_bf16.h>
#include <cstdint>
#include <math.h>

// Problem constants
constexpr int NN   = 20000;
constexpr int EE   = 320000;
constexpr int FF   = 256;
constexpr int HH   = 8;
constexpr int DD   = 64;
constexpr int HD   = 512;
constexpr int MM   = 2;
constexpr int CC   = 5;
constexpr int HIDN = 128;
constexpr int NB   = 80;

// ---------------- device scratch ----------------
__device__ float g_feat[MM][NN][HD];
__device__ float g_z[MM][NN][HD];
__device__ float g_el[MM][NN][HH];
__device__ float g_er[MM][NN][HH];
__device__ int   g_deg[MM][NN];
__device__ int   g_rowptr[MM][NN + 1];
__device__ int   g_cur[MM][NN];
__device__ int   g_csr_src[MM][EE];
__device__ float g_w[MM * NN];
__device__ float g_wsum[MM];
__device__ float g_beta[MM];
__device__ int   g_psum[MM][NB];
__device__ int   g_boff[MM][NB];
__device__ __nv_bfloat16 g_Wt_hi[MM][HD][FF];   // W transposed [n][k], hi part
__device__ __nv_bfloat16 g_Wt_lo[MM][HD][FF];
__device__ __nv_bfloat16 g_W1t_hi[HIDN][HD];    // sem_W1 transposed [n][k]
__device__ __nv_bfloat16 g_W1t_lo[HIDN][HD];

// ---------------- helpers ----------------
__device__ __forceinline__ uint32_t pack_bf2(float x, float y) {
    __nv_bfloat162 p = __floats2bfloat162_rn(x, y);
    return *(uint32_t*)&p;
}
__device__ __forceinline__ float bf_res(float x) {
    return x - __bfloat162float(__float2bfloat16(x));
}
__device__ __forceinline__ void split8(float4 a, float4 b, uint4& hi, uint4& lo) {
    hi.x = pack_bf2(a.x, a.y); hi.y = pack_bf2(a.z, a.w);
    hi.z = pack_bf2(b.x, b.y); hi.w = pack_bf2(b.z, b.w);
    lo.x = pack_bf2(bf_res(a.x), bf_res(a.y));
    lo.y = pack_bf2(bf_res(a.z), bf_res(a.w));
    lo.z = pack_bf2(bf_res(b.x), bf_res(b.y));
    lo.w = pack_bf2(bf_res(b.z), bf_res(b.w));
}
__device__ __forceinline__ float fast_tanh(float x) {
    float e2 = __expf(2.f * x);
    return __fdividef(e2 - 1.f, e2 + 1.f);
}
#define MMA_BF16(d, a, b) \
    asm volatile( \
        "mma.sync.aligned.m16n8k16.row.col.f32.bf16.bf16.f32 " \
        "{%0,%1,%2,%3}, {%4,%5,%6,%7}, {%8,%9}, {%0,%1,%2,%3};" \
        : "+f"((d)[0]), "+f"((d)[1]), "+f"((d)[2]), "+f"((d)[3]) \
        : "r"((a)[0]), "r"((a)[1]), "r"((a)[2]), "r"((a)[3]), \
          "r"((b)[0]), "r"((b)[1]))

// ---------------- weight conversion (one-time small transposes) -------------
__global__ void conv_w_kernel(const float* __restrict__ W) {
    __shared__ float tile[32][33];
    int mp = blockIdx.z;
    int n0 = blockIdx.x * 32, k0 = blockIdx.y * 32;
    int tx = threadIdx.x, ty = threadIdx.y;  // 32 x 8
#pragma unroll
    for (int j = 0; j < 4; j++)
        tile[ty + j * 8][tx] = W[mp * FF * HD + (k0 + ty + j * 8) * HD + n0 + tx];
    __syncthreads();
#pragma unroll
    for (int j = 0; j < 4; j++) {
        int n = n0 + ty + j * 8, k = k0 + tx;
        float x = tile[tx][ty + j * 8];
        g_Wt_hi[mp][n][k] = __float2bfloat16(x);
        g_Wt_lo[mp][n][k] = __float2bfloat16(bf_res(x));
    }
}

__global__ void conv_w1t_kernel(const float* __restrict__ W1) {
    __shared__ float tile[32][33];
    int n0 = blockIdx.x * 32, k0 = blockIdx.y * 32;
    int tx = threadIdx.x, ty = threadIdx.y;  // 32 x 8
#pragma unroll
    for (int j = 0; j < 4; j++)
        tile[ty + j * 8][tx] = W1[(k0 + ty + j * 8) * HIDN + n0 + tx];
    __syncthreads();
#pragma unroll
    for (int j = 0; j < 4; j++) {
        int n = n0 + ty + j * 8, k = k0 + tx;
        float x = tile[tx][ty + j * 8];
        g_W1t_hi[n][k] = __float2bfloat16(x);
        g_W1t_lo[n][k] = __float2bfloat16(bf_res(x));
    }
}

// ---------------- feat GEMM: K=256, resident hi/lo tiles, 3 products --------
// Block 128x64 (one head), 8 warps = 4(m) x 2(n), warp tile 32x32.
constexpr int FEAT_SMEM_BYTES = 55296 + 1536;

__global__ void __launch_bounds__(256, 2)
feat_mma_kernel(const float* __restrict__ h,
                const float* __restrict__ al, const float* __restrict__ ar) {
    extern __shared__ char smem[];
    __nv_bfloat16 (*Ah)[72] = (__nv_bfloat16(*)[72])(smem);
    __nv_bfloat16 (*Al)[72] = (__nv_bfloat16(*)[72])(smem + 18432);
    __nv_bfloat16 (*Bh)[72] = (__nv_bfloat16(*)[72])(smem + 36864);
    __nv_bfloat16 (*Bl)[72] = (__nv_bfloat16(*)[72])(smem + 46080);
    float* s_al = (float*)(smem + 55296);
    float* s_ar = s_al + 64;
    float* s_el = s_ar + 64;
    float* s_er = s_el + 128;

    const int t = threadIdx.x, lane = t & 31, wid = t >> 5;
    const int wm = wid & 3, wn = wid >> 2;
    const int rowBase = blockIdx.x * 128;
    const int head    = blockIdx.y;
    const int mp      = blockIdx.z;
    const int colBase = head * DD;

    if (t < 64) {
        s_al[t] = al[mp * HD + colBase + t];
        s_ar[t] = ar[mp * HD + colBase + t];
    }
    if (t < 128) { s_el[t] = 0.f; s_er[t] = 0.f; }

    float d[2][4][4] = {};

    for (int kc = 0; kc < 4; kc++) {
        // A: stage fp32 h -> hi/lo bf16. 128 rows x 8 chunks(8 floats) = 1024
#pragma unroll
        for (int j = 0; j < 4; j++) {
            int idx = t + j * 256;
            int row = idx >> 3, kq = (idx & 7) * 8;
            int grow = rowBase + row;
            float4 va = make_float4(0.f, 0.f, 0.f, 0.f), vb = va;
            if (grow < NN) {
                const float* hp = &h[grow * FF + kc * 64 + kq];
                va = *(const float4*)hp;
                vb = *(const float4*)(hp + 4);
            }
            uint4 hi, lo;
            split8(va, vb, hi, lo);
            *(uint4*)&Ah[row][kq] = hi;
            *(uint4*)&Al[row][kq] = lo;
        }
        // B: pre-split bf16. 64 rows x 8 chunks = 512
#pragma unroll
        for (int j = 0; j < 2; j++) {
            int idx = t + j * 256;
            int row = idx >> 3, kq = (idx & 7) * 8;
            *(uint4*)&Bh[row][kq] = *(const uint4*)&g_Wt_hi[mp][colBase + row][kc * 64 + kq];
            *(uint4*)&Bl[row][kq] = *(const uint4*)&g_Wt_lo[mp][colBase + row][kc * 64 + kq];
        }
        __syncthreads();

#pragma unroll
        for (int ks = 0; ks < 4; ks++) {
            const int kk = ks * 16 + (lane & 3) * 2;
            uint32_t ah[2][4], alr[2][4], bh[4][2], bl[4][2];
#pragma unroll
            for (int mi = 0; mi < 2; mi++) {
                int r = wm * 32 + mi * 16 + (lane >> 2);
                ah[mi][0] = *(const uint32_t*)&Ah[r][kk];
                ah[mi][1] = *(const uint32_t*)&Ah[r + 8][kk];
                ah[mi][2] = *(const uint32_t*)&Ah[r][kk + 8];
                ah[mi][3] = *(const uint32_t*)&Ah[r + 8][kk + 8];
                alr[mi][0] = *(const uint32_t*)&Al[r][kk];
                alr[mi][1] = *(const uint32_t*)&Al[r + 8][kk];
                alr[mi][2] = *(const uint32_t*)&Al[r][kk + 8];
                alr[mi][3] = *(const uint32_t*)&Al[r + 8][kk + 8];
            }
#pragma unroll
            for (int ni = 0; ni < 4; ni++) {
                int n = wn * 32 + ni * 8 + (lane >> 2);
                bh[ni][0] = *(const uint32_t*)&Bh[n][kk];
                bh[ni][1] = *(const uint32_t*)&Bh[n][kk + 8];
                bl[ni][0] = *(const uint32_t*)&Bl[n][kk];
                bl[ni][1] = *(const uint32_t*)&Bl[n][kk + 8];
            }
#pragma unroll
            for (int mi = 0; mi < 2; mi++)
#pragma unroll
                for (int ni = 0; ni < 4; ni++) {
                    MMA_BF16(d[mi][ni], ah[mi], bh[ni]);
                    MMA_BF16(d[mi][ni], ah[mi], bl[ni]);
                    MMA_BF16(d[mi][ni], alr[mi], bh[ni]);
                }
        }
        __syncthreads();
    }

    // ---- epilogue: write feat, reduce el/er ----
    const int c0base = wn * 32 + (lane & 3) * 2;
#pragma unroll
    for (int mi = 0; mi < 2; mi++) {
#pragma unroll
        for (int half = 0; half < 2; half++) {
            int r = wm * 32 + mi * 16 + half * 8 + (lane >> 2);
            int grow = rowBase + r;
            float el = 0.f, er = 0.f;
#pragma unroll
            for (int ni = 0; ni < 4; ni++) {
                float v0 = d[mi][ni][half * 2 + 0];
                float v1 = d[mi][ni][half * 2 + 1];
                int c = c0base + ni * 8;
                el += v0 * s_al[c] + v1 * s_al[c + 1];
                er += v0 * s_ar[c] + v1 * s_ar[c + 1];
                if (grow < NN)
                    *(float2*)&g_feat[mp][grow][colBase + c] = make_float2(v0, v1);
            }
            el += __shfl_xor_sync(0xffffffffu, el, 1);
            el += __shfl_xor_sync(0xffffffffu, el, 2);
            er += __shfl_xor_sync(0xffffffffu, er, 1);
            er += __shfl_xor_sync(0xffffffffu, er, 2);
            if ((lane & 3) == 0) {
                atomicAdd(&s_el[r], el);
                atomicAdd(&s_er[r], er);
            }
        }
    }
    __syncthreads();
    if (t < 128) {
        int grow = rowBase + t;
        if (grow < NN) {
            g_el[mp][grow][head] = s_el[t];
            g_er[mp][grow][head] = s_er[t];
        }
    }
}

// ---------------- CSR build ----------------
__global__ void count_kernel(const int* __restrict__ dst) {
    int mp = blockIdx.y;
    int e = blockIdx.x * blockDim.x + threadIdx.x;
    if (e < EE) atomicAdd(&g_deg[mp][dst[mp * EE + e]], 1);
}

__global__ void scan_partial() {
    int mp = blockIdx.y;
    int i = blockIdx.x * 256 + threadIdx.x;
    int v = (i < NN) ? g_deg[mp][i] : 0;
#pragma unroll
    for (int off = 16; off; off >>= 1) v += __shfl_xor_sync(0xffffffffu, v, off);
    __shared__ int ws[8];
    if ((threadIdx.x & 31) == 0) ws[threadIdx.x >> 5] = v;
    __syncthreads();
    if (threadIdx.x == 0) {
        int s = 0;
#pragma unroll
        for (int w = 0; w < 8; w++) s += ws[w];
        g_psum[mp][blockIdx.x] = s;
    }
}

__global__ void scan_mid() {
    int mp = blockIdx.x;
    int t = threadIdx.x, lane = t & 31, wid = t >> 5;
    int v = (t < NB) ? g_psum[mp][t] : 0;
    int x = v;
#pragma unroll
    for (int off = 1; off < 32; off <<= 1) {
        int y = __shfl_up_sync(0xffffffffu, x, off);
        if (lane >= off) x += y;
    }
    __shared__ int ws[4];
    if (lane == 31) ws[wid] = x;
    __syncthreads();
    int woff = 0;
    for (int w = 0; w < wid; w++) woff += ws[w];
    if (t < NB) g_boff[mp][t] = woff + x - v;
}

__global__ void scan_final() {
    int mp = blockIdx.y;
    int t = threadIdx.x, lane = t & 31, wid = t >> 5;
    int i = blockIdx.x * 256 + t;
    int v = (i < NN) ? g_deg[mp][i] : 0;
    int x = v;
#pragma unroll
    for (int off = 1; off < 32; off <<= 1) {
        int y = __shfl_up_sync(0xffffffffu, x, off);
        if (lane >= off) x += y;
    }
    __shared__ int ws[8];
    if (lane == 31) ws[wid] = x;
    __syncthreads();
    int woff = 0;
    for (int w = 0; w < wid; w++) woff += ws[w];
    int excl = g_boff[mp][blockIdx.x] + woff + x - v;
    if (i < NN) {
        g_rowptr[mp][i] = excl;
        g_cur[mp][i]    = excl;
        if (i == NN - 1) g_rowptr[mp][NN] = excl + v;
    }
}

__global__ void scatter_kernel(const int* __restrict__ src,
                               const int* __restrict__ dst) {
    int mp = blockIdx.y;
    int e = blockIdx.x * blockDim.x + threadIdx.x;
    if (e < EE) {
        int d = dst[mp * EE + e];
        int pos = atomicAdd(&g_cur[mp][d], 1);
        g_csr_src[mp][pos] = src[mp * EE + e];
    }
}

// ---------------- edge softmax + aggregation ----------------
__global__ void agg_kernel(const float* __restrict__ bias) {
    const int v  = blockIdx.x;
    const int mp = blockIdx.y;
    const int t  = threadIdx.x;  // 128

    __shared__ float ser[HH], sden[HH];
    __shared__ float sex[16][HH];
    __shared__ int   ssrc[16];

    const int start = g_rowptr[mp][v];
    const int deg   = g_rowptr[mp][v + 1] - start;

    if (t < HH) {
        ser[t]  = g_er[mp][v][t];
        sden[t] = 0.f;
    }
    __syncthreads();

    float acc0 = 0.f, acc1 = 0.f, acc2 = 0.f, acc3 = 0.f;
    const int d0  = t * 4;
    const int myh = t >> 4;

    for (int base = 0; base < deg; base += 16) {
        int cn = min(16, deg - base);
        if (t < cn * 8) {
            int i = t >> 3, hh = t & 7;
            int s = g_csr_src[mp][start + base + i];
            if (hh == 0) ssrc[i] = s;
            float e = g_el[mp][s][hh] + ser[hh];
            e = (e > 0.f) ? e : 0.2f * e;
            sex[i][hh] = __expf(e);
        }
        __syncthreads();
        if (t < 8) {
            float dsum = 0.f;
            for (int i = 0; i < cn; i++) dsum += sex[i][t];
            sden[t] += dsum;
        }
#pragma unroll 4
        for (int i = 0; i < cn; i++) {
            int s = ssrc[i];
            float w = sex[i][myh];
            float4 fv = *(const float4*)&g_feat[mp][s][d0];
            acc0 += w * fv.x;
            acc1 += w * fv.y;
            acc2 += w * fv.z;
            acc3 += w * fv.w;
        }
        __syncthreads();
    }

    float inv = 1.f / fmaxf(sden[myh], 1e-9f);
    const float* b = bias + mp * HD + d0;
    float o0 = acc0 * inv + b[0];
    float o1 = acc1 * inv + b[1];
    float o2 = acc2 * inv + b[2];
    float o3 = acc3 * inv + b[3];
    o0 = (o0 > 0.f) ? o0 : (__expf(o0) - 1.f);
    o1 = (o1 > 0.f) ? o1 : (__expf(o1) - 1.f);
    o2 = (o2 > 0.f) ? o2 : (__expf(o2) - 1.f);
    o3 = (o3 > 0.f) ? o3 : (__expf(o3) - 1.f);
    *(float4*)&g_z[mp][v][d0] = make_float4(o0, o1, o2, o3);
}

// ---------------- semantic attention via bf16 MMA (3 products) -------------
// rows 40000 (64/block, 625 blocks), N=128, K=512 (8 chunks of 64)
// 8 warps = 2(m) x 4(n), warp tile 32x32.
constexpr int SEM_SMEM_BYTES = 55296 + 1280;

__global__ void __launch_bounds__(256, 2)
sem_mma_kernel(const float* __restrict__ b1, const float* __restrict__ W2) {
    extern __shared__ char smem[];
    __nv_bfloat16 (*Ah)[72] = (__nv_bfloat16(*)[72])(smem);
    __nv_bfloat16 (*Al)[72] = (__nv_bfloat16(*)[72])(smem + 9216);
    __nv_bfloat16 (*Bh)[72] = (__nv_bfloat16(*)[72])(smem + 18432);
    __nv_bfloat16 (*Bl)[72] = (__nv_bfloat16(*)[72])(smem + 36864);
    float* s_b1 = (float*)(smem + 55296);
    float* s_w2 = s_b1 + 128;
    float* s_wr = s_w2 + 128;   // 64

    const int t = threadIdx.x, lane = t & 31, wid = t >> 5;
    const int wm = wid & 1, wn = wid >> 1;
    const int rowBase = blockIdx.x * 64;
    const float* Z = &g_z[0][0][0];   // [40000][512]

    if (t < 128) { s_b1[t] = b1[t]; s_w2[t] = W2[t]; }
    if (t < 64) s_wr[t] = 0.f;

    float d[2][4][4] = {};

    for (int kc = 0; kc < 8; kc++) {
        // A: stage fp32 z -> hi/lo. 64 rows x 8 chunks = 512
#pragma unroll
        for (int j = 0; j < 2; j++) {
            int idx = t + j * 256;
            int row = idx >> 3, kq = (idx & 7) * 8;
            const float* zp = &Z[(rowBase + row) * HD + kc * 64 + kq];
            float4 va = *(const float4*)zp;
            float4 vb = *(const float4*)(zp + 4);
            uint4 hi, lo;
            split8(va, vb, hi, lo);
            *(uint4*)&Ah[row][kq] = hi;
            *(uint4*)&Al[row][kq] = lo;
        }
        // B: pre-split W1t. 128 rows x 8 chunks = 1024
#pragma unroll
        for (int j = 0; j < 4; j++) {
            int idx = t + j * 256;
            int row = idx >> 3, kq = (idx & 7) * 8;
            *(uint4*)&Bh[row][kq] = *(const uint4*)&g_W1t_hi[row][kc * 64 + kq];
            *(uint4*)&Bl[row][kq] = *(const uint4*)&g_W1t_lo[row][kc * 64 + kq];
        }
        __syncthreads();

#pragma unroll
        for (int ks = 0; ks < 4; ks++) {
            const int kk = ks * 16 + (lane & 3) * 2;
            uint32_t ah[2][4], alr[2][4], bh[4][2], bl[4][2];
#pragma unroll
            for (int mi = 0; mi < 2; mi++) {
                int r = wm * 32 + mi * 16 + (lane >> 2);
                ah[mi][0] = *(const uint32_t*)&Ah[r][kk];
                ah[mi][1] = *(const uint32_t*)&Ah[r + 8][kk];
                ah[mi][2] = *(const uint32_t*)&Ah[r][kk + 8];
                ah[mi][3] = *(const uint32_t*)&Ah[r + 8][kk + 8];
                alr[mi][0] = *(const uint32_t*)&Al[r][kk];
                alr[mi][1] = *(const uint32_t*)&Al[r + 8][kk];
                alr[mi][2] = *(const uint32_t*)&Al[r][kk + 8];
                alr[mi][3] = *(const uint32_t*)&Al[r + 8][kk + 8];
            }
#pragma unroll
            for (int ni = 0; ni < 4; ni++) {
                int n = wn * 32 + ni * 8 + (lane >> 2);
                bh[ni][0] = *(const uint32_t*)&Bh[n][kk];
                bh[ni][1] = *(const uint32_t*)&Bh[n][kk + 8];
                bl[ni][0] = *(const uint32_t*)&Bl[n][kk];
                bl[ni][1] = *(const uint32_t*)&Bl[n][kk + 8];
            }
#pragma unroll
            for (int mi = 0; mi < 2; mi++)
#pragma unroll
                for (int ni = 0; ni < 4; ni++) {
                    MMA_BF16(d[mi][ni], ah[mi], bh[ni]);
                    MMA_BF16(d[mi][ni], ah[mi], bl[ni]);
                    MMA_BF16(d[mi][ni], alr[mi], bh[ni]);
                }
        }
        __syncthreads();
    }

    // epilogue: w[row] = sum_c tanh(acc + b1[c]) * W2[c]
#pragma unroll
    for (int mi = 0; mi < 2; mi++) {
#pragma unroll
        for (int half = 0; half < 2; half++) {
            float p = 0.f;
#pragma unroll
            for (int ni = 0; ni < 4; ni++) {
                int c = wn * 32 + ni * 8 + (lane & 3) * 2;
                p += fast_tanh(d[mi][ni][half * 2 + 0] + s_b1[c]) * s_w2[c];
                p += fast_tanh(d[mi][ni][half * 2 + 1] + s_b1[c + 1]) * s_w2[c + 1];
            }
            p += __shfl_xor_sync(0xffffffffu, p, 1);
            p += __shfl_xor_sync(0xffffffffu, p, 2);
            if ((lane & 3) == 0)
                atomicAdd(&s_wr[wm * 32 + mi * 16 + half * 8 + (lane >> 2)], p);
        }
    }
    __syncthreads();
    if (t < 64) g_w[rowBase + t] = s_wr[t];
}

__global__ void wsum_kernel() {
    __shared__ float sp[MM];
    if (threadIdx.x < MM) sp[threadIdx.x] = 0.f;
    __syncthreads();
    int i = blockIdx.x * blockDim.x + threadIdx.x;
    if (i < MM * NN) atomicAdd(&sp[i / NN], g_w[i]);
    __syncthreads();
    if (threadIdx.x < MM) atomicAdd(&g_wsum[threadIdx.x], sp[threadIdx.x]);
}

__global__ void beta_kernel() {
    float a = g_wsum[0] / (float)NN;
    float b = g_wsum[1] / (float)NN;
    float m = fmaxf(a, b);
    float ea = __expf(a - m), eb = __expf(b - m);
    float s = ea + eb;
    g_beta[0] = ea / s;
    g_beta[1] = eb / s;
}

__global__ void pred_kernel(const float* __restrict__ pw,
                            const float* __restrict__ pb,
                            float* __restrict__ out) {
    int gwarp = (blockIdx.x * blockDim.x + threadIdx.x) >> 5;
    int lane  = threadIdx.x & 31;
    if (gwarp >= NN) return;
    float b0 = g_beta[0], b1 = g_beta[1];
    float acc[CC];
#pragma unroll
    for (int c = 0; c < CC; c++) acc[c] = 0.f;
    const float* z0 = g_z[0][gwarp];
    const float* z1 = g_z[1][gwarp];
    for (int d = lane; d < HD; d += 32) {
        float hv = b0 * z0[d] + b1 * z1[d];
#pragma unroll
        for (int c = 0; c < CC; c++) acc[c] += hv * __ldg(&pw[d * CC + c]);
    }
#pragma unroll
    for (int off = 16; off; off >>= 1)
#pragma unroll
        for (int c = 0; c < CC; c++)
            acc[c] += __shfl_xor_sync(0xffffffffu, acc[c], off);
    if (lane == 0) {
#pragma unroll
        for (int c = 0; c < CC; c++) out[gwarp * CC + c] = acc[c] + pb[c];
    }
}

// ---------------- launch ----------------
extern "C" void kernel_launch(void* const* d_in, const int* in_sizes, int n_in,
                              void* d_out, int out_size) {
    const float* h      = (const float*)d_in[0];
    const int*   src    = (const int*)d_in[1];
    const int*   dst    = (const int*)d_in[2];
    const float* W      = (const float*)d_in[3];
    const float* attn_l = (const float*)d_in[4];
    const float* attn_r = (const float*)d_in[5];
    const float* bias_g = (const float*)d_in[6];
    const float* sem_W1 = (const float*)d_in[7];
    const float* sem_b1 = (const float*)d_in[8];
    const float* sem_W2 = (const float*)d_in[9];
    const float* pred_W = (const float*)d_in[10];
    const float* pred_b = (const float*)d_in[11];
    float* out = (float*)d_out;

    cudaFuncSetAttribute(feat_mma_kernel,
                         cudaFuncAttributeMaxDynamicSharedMemorySize, FEAT_SMEM_BYTES);
    cudaFuncSetAttribute(sem_mma_kernel,
                         cudaFuncAttributeMaxDynamicSharedMemorySize, SEM_SMEM_BYTES);

    void* p_deg = nullptr;
    void* p_ws  = nullptr;
    cudaGetSymbolAddress(&p_deg, g_deg);
    cudaGetSymbolAddress(&p_ws, g_wsum);
    cudaMemsetAsync(p_deg, 0, sizeof(int) * MM * NN, 0);        // launch 1
    cudaMemsetAsync(p_ws, 0, sizeof(float) * MM, 0);            // launch 2

    {
        dim3 grid(HD / 32, FF / 32, MM);
        conv_w_kernel<<<grid, dim3(32, 8)>>>(W);                // launch 3
    }
    conv_w1t_kernel<<<dim3(HIDN / 32, HD / 32), dim3(32, 8)>>>(sem_W1);  // launch 4
    {
        dim3 grid((EE + 255) / 256, MM);
        count_kernel<<<grid, 256>>>(dst);                       // launch 5
    }
    {
        dim3 grid((NN + 127) / 128, HH, MM);
        feat_mma_kernel<<<grid, 256, FEAT_SMEM_BYTES>>>(h, attn_l, attn_r);  // launch 6
    }
    scan_partial<<<dim3(NB, MM), 256>>>();
    scan_mid<<<MM, 128>>>();
    scan_final<<<dim3(NB, MM), 256>>>();
    {
        dim3 grid((EE + 255) / 256, MM);
        scatter_kernel<<<grid, 256>>>(src, dst);
    }
    {
        dim3 grid(NN, MM);
        agg_kernel<<<grid, 128>>>(bias_g);
    }
    sem_mma_kernel<<<(MM * NN) / 64, 256, SEM_SMEM_BYTES>>>(sem_b1, sem_W2);
    wsum_kernel<<<(MM * NN + 255) / 256, 256>>>();
    beta_kernel<<<1, 1>>>();
    pred_kernel<<<(NN * 32 + 255) / 256, 256>>>(pred_W, pred_b, out);
}

// round 7
// speedup vs baseline: 2.6631x; 1.2612x over previous
#include <cuda_runtime.h>
#include <cuda_bf16.h>
#include <cuda_fp16.h>
#include <cstdint>
#include <math.h>

// Problem constants
constexpr int NN   = 20000;
constexpr int EE   = 320000;
constexpr int FF   = 256;
constexpr int HH   = 8;
constexpr int DD   = 64;
constexpr int HD   = 512;
constexpr int MM   = 2;
constexpr int CC   = 5;
constexpr int HIDN = 128;
constexpr int NB   = 80;

// ---------------- device scratch ----------------
__device__ __half g_feat_h[MM][NN][HD];
__device__ __half g_z_h[MM][NN][HD];
__device__ float g_el[MM][NN][HH];
__device__ float g_er[MM][NN][HH];
__device__ int   g_deg[MM][NN];
__device__ int   g_rowptr[MM][NN + 1];
__device__ int   g_cur[MM][NN];
__device__ int   g_csr_src[MM][EE];
__device__ float g_w[MM * NN];
__device__ float g_wsum[MM];
__device__ float g_beta[MM];
__device__ int   g_psum[MM][NB];
__device__ int   g_boff[MM][NB];
__device__ __nv_bfloat16 g_Wt_hi[MM][HD][FF];   // W transposed [n][k], hi
__device__ __nv_bfloat16 g_Wt_lo[MM][HD][FF];
__device__ __nv_bfloat16 g_W1t_hi[HIDN][HD];    // sem_W1 transposed [n][k]

// ---------------- helpers ----------------
__device__ __forceinline__ uint32_t pack_bf2(float x, float y) {
    __nv_bfloat162 p = __floats2bfloat162_rn(x, y);
    return *(uint32_t*)&p;
}
__device__ __forceinline__ float bf_res(float x) {
    return x - __bfloat162float(__float2bfloat16(x));
}
__device__ __forceinline__ void split8(float4 a, float4 b, uint4& hi, uint4& lo) {
    hi.x = pack_bf2(a.x, a.y); hi.y = pack_bf2(a.z, a.w);
    hi.z = pack_bf2(b.x, b.y); hi.w = pack_bf2(b.z, b.w);
    lo.x = pack_bf2(bf_res(a.x), bf_res(a.y));
    lo.y = pack_bf2(bf_res(a.z), bf_res(a.w));
    lo.z = pack_bf2(bf_res(b.x), bf_res(b.y));
    lo.w = pack_bf2(bf_res(b.z), bf_res(b.w));
}
__device__ __forceinline__ float fast_tanh(float x) {
    float e2 = __expf(2.f * x);
    return __fdividef(e2 - 1.f, e2 + 1.f);
}
#define MMA_BF16(d, a, b) \
    asm volatile( \
        "mma.sync.aligned.m16n8k16.row.col.f32.bf16.bf16.f32 " \
        "{%0,%1,%2,%3}, {%4,%5,%6,%7}, {%8,%9}, {%0,%1,%2,%3};" \
        : "+f"((d)[0]), "+f"((d)[1]), "+f"((d)[2]), "+f"((d)[3]) \
        : "r"((a)[0]), "r"((a)[1]), "r"((a)[2]), "r"((a)[3]), \
          "r"((b)[0]), "r"((b)[1]))

// ---------------- weight conversion ----------------
__global__ void conv_w_kernel(const float* __restrict__ W) {
    __shared__ float tile[32][33];
    int mp = blockIdx.z;
    int n0 = blockIdx.x * 32, k0 = blockIdx.y * 32;
    int tx = threadIdx.x, ty = threadIdx.y;  // 32 x 8
#pragma unroll
    for (int j = 0; j < 4; j++)
        tile[ty + j * 8][tx] = W[mp * FF * HD + (k0 + ty + j * 8) * HD + n0 + tx];
    __syncthreads();
#pragma unroll
    for (int j = 0; j < 4; j++) {
        int n = n0 + ty + j * 8, k = k0 + tx;
        float x = tile[tx][ty + j * 8];
        g_Wt_hi[mp][n][k] = __float2bfloat16(x);
        g_Wt_lo[mp][n][k] = __float2bfloat16(bf_res(x));
    }
}

__global__ void conv_w1t_kernel(const float* __restrict__ W1) {
    __shared__ float tile[32][33];
    int n0 = blockIdx.x * 32, k0 = blockIdx.y * 32;
    int tx = threadIdx.x, ty = threadIdx.y;
#pragma unroll
    for (int j = 0; j < 4; j++)
        tile[ty + j * 8][tx] = W1[(k0 + ty + j * 8) * HIDN + n0 + tx];
    __syncthreads();
#pragma unroll
    for (int j = 0; j < 4; j++) {
        int n = n0 + ty + j * 8, k = k0 + tx;
        g_W1t_hi[n][k] = __float2bfloat16(tile[tx][ty + j * 8]);
    }
}

// ---------------- feat GEMM: 128x128 block (2 heads), warp tile 32x64 -------
constexpr int FEAT_SMEM_BYTES = 4 * 18432 + 1024;

__global__ void __launch_bounds__(256)
feat_mma_kernel(const float* __restrict__ h,
                const float* __restrict__ al, const float* __restrict__ ar) {
    extern __shared__ char smem[];
    __nv_bfloat16 (*Ah)[72] = (__nv_bfloat16(*)[72])(smem);
    __nv_bfloat16 (*Al)[72] = (__nv_bfloat16(*)[72])(smem + 18432);
    __nv_bfloat16 (*Bh)[72] = (__nv_bfloat16(*)[72])(smem + 36864);
    __nv_bfloat16 (*Bl)[72] = (__nv_bfloat16(*)[72])(smem + 55296);
    float* s_al = (float*)(smem + 73728);   // 128
    float* s_ar = s_al + 128;

    const int t = threadIdx.x, lane = t & 31, wid = t >> 5;
    const int wm = wid & 3, wn = wid >> 2;        // 4(m) x 2(n)
    const int rowBase = blockIdx.x * 128;
    const int colBase = blockIdx.y * 128;          // 2 heads
    const int mp      = blockIdx.z;

    if (t < 128) {
        s_al[t] = al[mp * HD + colBase + t];
        s_ar[t] = ar[mp * HD + colBase + t];
    }

    float d[2][8][4] = {};

    for (int kc = 0; kc < 4; kc++) {
        // A: 128 rows x 64 k fp32 -> hi/lo bf16
#pragma unroll
        for (int j = 0; j < 4; j++) {
            int idx = t + j * 256;
            int row = idx >> 3, kq = (idx & 7) * 8;
            int grow = rowBase + row;
            float4 va = make_float4(0.f, 0.f, 0.f, 0.f), vb = va;
            if (grow < NN) {
                const float* hp = &h[grow * FF + kc * 64 + kq];
                va = *(const float4*)hp;
                vb = *(const float4*)(hp + 4);
            }
            uint4 hi, lo;
            split8(va, vb, hi, lo);
            *(uint4*)&Ah[row][kq] = hi;
            *(uint4*)&Al[row][kq] = lo;
        }
        // B: 128 cols x 64 k pre-split bf16
#pragma unroll
        for (int j = 0; j < 4; j++) {
            int idx = t + j * 256;
            int row = idx >> 3, kq = (idx & 7) * 8;
            *(uint4*)&Bh[row][kq] = *(const uint4*)&g_Wt_hi[mp][colBase + row][kc * 64 + kq];
            *(uint4*)&Bl[row][kq] = *(const uint4*)&g_Wt_lo[mp][colBase + row][kc * 64 + kq];
        }
        __syncthreads();

#pragma unroll
        for (int ks = 0; ks < 4; ks++) {
            const int kk = ks * 16 + (lane & 3) * 2;
            uint32_t ah[2][4], alr[2][4], bh[8][2], bl[8][2];
#pragma unroll
            for (int mi = 0; mi < 2; mi++) {
                int r = wm * 32 + mi * 16 + (lane >> 2);
                ah[mi][0] = *(const uint32_t*)&Ah[r][kk];
                ah[mi][1] = *(const uint32_t*)&Ah[r + 8][kk];
                ah[mi][2] = *(const uint32_t*)&Ah[r][kk + 8];
                ah[mi][3] = *(const uint32_t*)&Ah[r + 8][kk + 8];
                alr[mi][0] = *(const uint32_t*)&Al[r][kk];
                alr[mi][1] = *(const uint32_t*)&Al[r + 8][kk];
                alr[mi][2] = *(const uint32_t*)&Al[r][kk + 8];
                alr[mi][3] = *(const uint32_t*)&Al[r + 8][kk + 8];
            }
#pragma unroll
            for (int ni = 0; ni < 8; ni++) {
                int n = wn * 64 + ni * 8 + (lane >> 2);
                bh[ni][0] = *(const uint32_t*)&Bh[n][kk];
                bh[ni][1] = *(const uint32_t*)&Bh[n][kk + 8];
                bl[ni][0] = *(const uint32_t*)&Bl[n][kk];
                bl[ni][1] = *(const uint32_t*)&Bl[n][kk + 8];
            }
#pragma unroll
            for (int mi = 0; mi < 2; mi++)
#pragma unroll
                for (int ni = 0; ni < 8; ni++) {
                    MMA_BF16(d[mi][ni], ah[mi], bh[ni]);
                    MMA_BF16(d[mi][ni], ah[mi], bl[ni]);
                    MMA_BF16(d[mi][ni], alr[mi], bh[ni]);
                }
        }
        __syncthreads();
    }

    // ---- epilogue: each warp's 64 cols = one head; el/er reduce in-warp ----
    const int head = colBase / DD + wn;     // global head of this warp
#pragma unroll
    for (int mi = 0; mi < 2; mi++) {
#pragma unroll
        for (int half = 0; half < 2; half++) {
            int r = wm * 32 + mi * 16 + half * 8 + (lane >> 2);
            int grow = rowBase + r;
            float el = 0.f, er = 0.f;
#pragma unroll
            for (int ni = 0; ni < 8; ni++) {
                float v0 = d[mi][ni][half * 2 + 0];
                float v1 = d[mi][ni][half * 2 + 1];
                int c = wn * 64 + ni * 8 + (lane & 3) * 2;   // block-local col
                el += v0 * s_al[c] + v1 * s_al[c + 1];
                er += v0 * s_ar[c] + v1 * s_ar[c + 1];
                if (grow < NN) {
                    __half2 hv = __floats2half2_rn(v0, v1);
                    *(__half2*)&g_feat_h[mp][grow][colBase + c] = hv;
                }
            }
            el += __shfl_xor_sync(0xffffffffu, el, 1);
            el += __shfl_xor_sync(0xffffffffu, el, 2);
            er += __shfl_xor_sync(0xffffffffu, er, 1);
            er += __shfl_xor_sync(0xffffffffu, er, 2);
            if ((lane & 3) == 0 && grow < NN) {
                g_el[mp][grow][head] = el;
                g_er[mp][grow][head] = er;
            }
        }
    }
}

// ---------------- CSR build ----------------
__global__ void count_kernel(const int* __restrict__ dst) {
    int mp = blockIdx.y;
    int e = blockIdx.x * blockDim.x + threadIdx.x;
    if (e < EE) atomicAdd(&g_deg[mp][dst[mp * EE + e]], 1);
}

__global__ void scan_partial() {
    int mp = blockIdx.y;
    int i = blockIdx.x * 256 + threadIdx.x;
    int v = (i < NN) ? g_deg[mp][i] : 0;
#pragma unroll
    for (int off = 16; off; off >>= 1) v += __shfl_xor_sync(0xffffffffu, v, off);
    __shared__ int ws[8];
    if ((threadIdx.x & 31) == 0) ws[threadIdx.x >> 5] = v;
    __syncthreads();
    if (threadIdx.x == 0) {
        int s = 0;
#pragma unroll
        for (int w = 0; w < 8; w++) s += ws[w];
        g_psum[mp][blockIdx.x] = s;
    }
}

__global__ void scan_mid() {
    int mp = blockIdx.x;
    int t = threadIdx.x, lane = t & 31, wid = t >> 5;
    int v = (t < NB) ? g_psum[mp][t] : 0;
    int x = v;
#pragma unroll
    for (int off = 1; off < 32; off <<= 1) {
        int y = __shfl_up_sync(0xffffffffu, x, off);
        if (lane >= off) x += y;
    }
    __shared__ int ws[4];
    if (lane == 31) ws[wid] = x;
    __syncthreads();
    int woff = 0;
    for (int w = 0; w < wid; w++) woff += ws[w];
    if (t < NB) g_boff[mp][t] = woff + x - v;
}

__global__ void scan_final() {
    int mp = blockIdx.y;
    int t = threadIdx.x, lane = t & 31, wid = t >> 5;
    int i = blockIdx.x * 256 + t;
    int v = (i < NN) ? g_deg[mp][i] : 0;
    int x = v;
#pragma unroll
    for (int off = 1; off < 32; off <<= 1) {
        int y = __shfl_up_sync(0xffffffffu, x, off);
        if (lane >= off) x += y;
    }
    __shared__ int ws[8];
    if (lane == 31) ws[wid] = x;
    __syncthreads();
    int woff = 0;
    for (int w = 0; w < wid; w++) woff += ws[w];
    int excl = g_boff[mp][blockIdx.x] + woff + x - v;
    if (i < NN) {
        g_rowptr[mp][i] = excl;
        g_cur[mp][i]    = excl;
        if (i == NN - 1) g_rowptr[mp][NN] = excl + v;
    }
}

__global__ void scatter_kernel(const int* __restrict__ src,
                               const int* __restrict__ dst) {
    int mp = blockIdx.y;
    int e = blockIdx.x * blockDim.x + threadIdx.x;
    if (e < EE) {
        int d = dst[mp * EE + e];
        int pos = atomicAdd(&g_cur[mp][d], 1);
        g_csr_src[mp][pos] = src[mp * EE + e];
    }
}

// ---------------- edge softmax + aggregation (fp16 feat) --------------------
__global__ void agg_kernel(const float* __restrict__ bias) {
    const int v  = blockIdx.x;
    const int mp = blockIdx.y;
    const int t  = threadIdx.x;  // 128

    __shared__ float ser[HH], sden[HH];
    __shared__ float sex[16][HH];
    __shared__ int   ssrc[16];

    const int start = g_rowptr[mp][v];
    const int deg   = g_rowptr[mp][v + 1] - start;

    if (t < HH) {
        ser[t]  = g_er[mp][v][t];
        sden[t] = 0.f;
    }
    __syncthreads();

    float acc0 = 0.f, acc1 = 0.f, acc2 = 0.f, acc3 = 0.f;
    const int d0  = t * 4;
    const int myh = t >> 4;

    for (int base = 0; base < deg; base += 16) {
        int cn = min(16, deg - base);
        if (t < cn * 8) {
            int i = t >> 3, hh = t & 7;
            int s = g_csr_src[mp][start + base + i];
            if (hh == 0) ssrc[i] = s;
            float e = g_el[mp][s][hh] + ser[hh];
            e = (e > 0.f) ? e : 0.2f * e;
            sex[i][hh] = __expf(e);
        }
        __syncthreads();
        if (t < 8) {
            float dsum = 0.f;
            for (int i = 0; i < cn; i++) dsum += sex[i][t];
            sden[t] += dsum;
        }
#pragma unroll 4
        for (int i = 0; i < cn; i++) {
            int s = ssrc[i];
            float w = sex[i][myh];
            uint2 raw = *(const uint2*)&g_feat_h[mp][s][d0];
            float2 f01 = __half22float2(*(__half2*)&raw.x);
            float2 f23 = __half22float2(*(__half2*)&raw.y);
            acc0 += w * f01.x;
            acc1 += w * f01.y;
            acc2 += w * f23.x;
            acc3 += w * f23.y;
        }
        __syncthreads();
    }

    float inv = 1.f / fmaxf(sden[myh], 1e-9f);
    const float* b = bias + mp * HD + d0;
    float o0 = acc0 * inv + b[0];
    float o1 = acc1 * inv + b[1];
    float o2 = acc2 * inv + b[2];
    float o3 = acc3 * inv + b[3];
    o0 = (o0 > 0.f) ? o0 : (__expf(o0) - 1.f);
    o1 = (o1 > 0.f) ? o1 : (__expf(o1) - 1.f);
    o2 = (o2 > 0.f) ? o2 : (__expf(o2) - 1.f);
    o3 = (o3 > 0.f) ? o3 : (__expf(o3) - 1.f);
    uint2 zout;
    *(__half2*)&zout.x = __floats2half2_rn(o0, o1);
    *(__half2*)&zout.y = __floats2half2_rn(o2, o3);
    *(uint2*)&g_z_h[mp][v][d0] = zout;
}

// ---------------- semantic attention: single-product bf16 MMA ---------------
// Block 64 rows x 128 cols, K=512 (8 chunks), warps 2(m) x 4(n), tile 32x32.
constexpr int SEM_SMEM_BYTES = 9216 + 18432 + 1280;

__global__ void __launch_bounds__(256)
sem_mma_kernel(const float* __restrict__ b1, const float* __restrict__ W2) {
    extern __shared__ char smem[];
    __nv_bfloat16 (*Ah)[72] = (__nv_bfloat16(*)[72])(smem);
    __nv_bfloat16 (*Bh)[72] = (__nv_bfloat16(*)[72])(smem + 9216);
    float* s_b1 = (float*)(smem + 27648);
    float* s_w2 = s_b1 + 128;
    float* s_wr = s_w2 + 128;

    const int t = threadIdx.x, lane = t & 31, wid = t >> 5;
    const int wm = wid & 1, wn = wid >> 1;
    const int rowBase = blockIdx.x * 64;
    const __half* Zh = &g_z_h[0][0][0];   // [40000][512]

    if (t < 128) { s_b1[t] = b1[t]; s_w2[t] = W2[t]; }
    if (t < 64) s_wr[t] = 0.f;

    float d[2][4][4] = {};

    for (int kc = 0; kc < 8; kc++) {
        // A: fp16 z -> bf16. 64 rows x 8 chunks = 512
#pragma unroll
        for (int j = 0; j < 2; j++) {
            int idx = t + j * 256;
            int row = idx >> 3, kq = (idx & 7) * 8;
            uint4 raw = *(const uint4*)&Zh[(rowBase + row) * HD + kc * 64 + kq];
            float2 f0 = __half22float2(*(__half2*)&raw.x);
            float2 f1 = __half22float2(*(__half2*)&raw.y);
            float2 f2 = __half22float2(*(__half2*)&raw.z);
            float2 f3 = __half22float2(*(__half2*)&raw.w);
            uint4 hi;
            hi.x = pack_bf2(f0.x, f0.y); hi.y = pack_bf2(f1.x, f1.y);
            hi.z = pack_bf2(f2.x, f2.y); hi.w = pack_bf2(f3.x, f3.y);
            *(uint4*)&Ah[row][kq] = hi;
        }
        // B: 128 x 64
#pragma unroll
        for (int j = 0; j < 4; j++) {
            int idx = t + j * 256;
            int row = idx >> 3, kq = (idx & 7) * 8;
            *(uint4*)&Bh[row][kq] = *(const uint4*)&g_W1t_hi[row][kc * 64 + kq];
        }
        __syncthreads();

#pragma unroll
        for (int ks = 0; ks < 4; ks++) {
            const int kk = ks * 16 + (lane & 3) * 2;
            uint32_t ah[2][4], bh[4][2];
#pragma unroll
            for (int mi = 0; mi < 2; mi++) {
                int r = wm * 32 + mi * 16 + (lane >> 2);
                ah[mi][0] = *(const uint32_t*)&Ah[r][kk];
                ah[mi][1] = *(const uint32_t*)&Ah[r + 8][kk];
                ah[mi][2] = *(const uint32_t*)&Ah[r][kk + 8];
                ah[mi][3] = *(const uint32_t*)&Ah[r + 8][kk + 8];
            }
#pragma unroll
            for (int ni = 0; ni < 4; ni++) {
                int n = wn * 32 + ni * 8 + (lane >> 2);
                bh[ni][0] = *(const uint32_t*)&Bh[n][kk];
                bh[ni][1] = *(const uint32_t*)&Bh[n][kk + 8];
            }
#pragma unroll
            for (int mi = 0; mi < 2; mi++)
#pragma unroll
                for (int ni = 0; ni < 4; ni++)
                    MMA_BF16(d[mi][ni], ah[mi], bh[ni]);
        }
        __syncthreads();
    }

    // epilogue: w[row] = sum_c tanh(acc + b1[c]) * W2[c]
#pragma unroll
    for (int mi = 0; mi < 2; mi++) {
#pragma unroll
        for (int half = 0; half < 2; half++) {
            float p = 0.f;
#pragma unroll
            for (int ni = 0; ni < 4; ni++) {
                int c = wn * 32 + ni * 8 + (lane & 3) * 2;
                p += fast_tanh(d[mi][ni][half * 2 + 0] + s_b1[c]) * s_w2[c];
                p += fast_tanh(d[mi][ni][half * 2 + 1] + s_b1[c + 1]) * s_w2[c + 1];
            }
            p += __shfl_xor_sync(0xffffffffu, p, 1);
            p += __shfl_xor_sync(0xffffffffu, p, 2);
            if ((lane & 3) == 0)
                atomicAdd(&s_wr[wm * 32 + mi * 16 + half * 8 + (lane >> 2)], p);
        }
    }
    __syncthreads();
    if (t < 64) g_w[rowBase + t] = s_wr[t];
}

__global__ void wsum_kernel() {
    __shared__ float sp[MM];
    if (threadIdx.x < MM) sp[threadIdx.x] = 0.f;
    __syncthreads();
    int i = blockIdx.x * blockDim.x + threadIdx.x;
    if (i < MM * NN) atomicAdd(&sp[i / NN], g_w[i]);
    __syncthreads();
    if (threadIdx.x < MM) atomicAdd(&g_wsum[threadIdx.x], sp[threadIdx.x]);
}

__global__ void beta_kernel() {
    float a = g_wsum[0] / (float)NN;
    float b = g_wsum[1] / (float)NN;
    float m = fmaxf(a, b);
    float ea = __expf(a - m), eb = __expf(b - m);
    float s = ea + eb;
    g_beta[0] = ea / s;
    g_beta[1] = eb / s;
}

__global__ void pred_kernel(const float* __restrict__ pw,
                            const float* __restrict__ pb,
                            float* __restrict__ out) {
    int gwarp = (blockIdx.x * blockDim.x + threadIdx.x) >> 5;
    int lane  = threadIdx.x & 31;
    if (gwarp >= NN) return;
    float b0 = g_beta[0], b1 = g_beta[1];
    float acc[CC];
#pragma unroll
    for (int c = 0; c < CC; c++) acc[c] = 0.f;
    const __half2* z0 = (const __half2*)g_z_h[0][gwarp];
    const __half2* z1 = (const __half2*)g_z_h[1][gwarp];
#pragma unroll
    for (int i = 0; i < HD / 64; i++) {
        int d2 = lane + i * 32;          // half2 index
        float2 f0 = __half22float2(z0[d2]);
        float2 f1 = __half22float2(z1[d2]);
        float hv0 = b0 * f0.x + b1 * f1.x;
        float hv1 = b0 * f0.y + b1 * f1.y;
        int dd = d2 * 2;
#pragma unroll
        for (int c = 0; c < CC; c++)
            acc[c] += hv0 * __ldg(&pw[dd * CC + c]) + hv1 * __ldg(&pw[(dd + 1) * CC + c]);
    }
#pragma unroll
    for (int off = 16; off; off >>= 1)
#pragma unroll
        for (int c = 0; c < CC; c++)
            acc[c] += __shfl_xor_sync(0xffffffffu, acc[c], off);
    if (lane == 0) {
#pragma unroll
        for (int c = 0; c < CC; c++) out[gwarp * CC + c] = acc[c] + pb[c];
    }
}

// ---------------- launch ----------------
extern "C" void kernel_launch(void* const* d_in, const int* in_sizes, int n_in,
                              void* d_out, int out_size) {
    const float* h      = (const float*)d_in[0];
    const int*   src    = (const int*)d_in[1];
    const int*   dst    = (const int*)d_in[2];
    const float* W      = (const float*)d_in[3];
    const float* attn_l = (const float*)d_in[4];
    const float* attn_r = (const float*)d_in[5];
    const float* bias_g = (const float*)d_in[6];
    const float* sem_W1 = (const float*)d_in[7];
    const float* sem_b1 = (const float*)d_in[8];
    const float* sem_W2 = (const float*)d_in[9];
    const float* pred_W = (const float*)d_in[10];
    const float* pred_b = (const float*)d_in[11];
    float* out = (float*)d_out;

    static cudaStream_t s2 = nullptr;
    static cudaEvent_t ev_fork = nullptr, ev_join = nullptr;
    if (s2 == nullptr) {
        cudaStreamCreateWithFlags(&s2, cudaStreamNonBlocking);
        cudaEventCreateWithFlags(&ev_fork, cudaEventDisableTiming);
        cudaEventCreateWithFlags(&ev_join, cudaEventDisableTiming);
    }

    cudaFuncSetAttribute(feat_mma_kernel,
                         cudaFuncAttributeMaxDynamicSharedMemorySize, FEAT_SMEM_BYTES);
    cudaFuncSetAttribute(sem_mma_kernel,
                         cudaFuncAttributeMaxDynamicSharedMemorySize, SEM_SMEM_BYTES);

    void* p_deg = nullptr;
    void* p_ws  = nullptr;
    cudaGetSymbolAddress(&p_deg, g_deg);
    cudaGetSymbolAddress(&p_ws, g_wsum);
    cudaMemsetAsync(p_deg, 0, sizeof(int) * MM * NN, 0);        // launch 1
    cudaMemsetAsync(p_ws, 0, sizeof(float) * MM, 0);            // launch 2

    {
        dim3 grid(HD / 32, FF / 32, MM);
        conv_w_kernel<<<grid, dim3(32, 8)>>>(W);                // launch 3
    }
    conv_w1t_kernel<<<dim3(HIDN / 32, HD / 32), dim3(32, 8)>>>(sem_W1);  // launch 4

    // fork: CSR chain on s2, concurrent with feat_mma on stream 0
    cudaEventRecord(ev_fork, 0);
    cudaStreamWaitEvent(s2, ev_fork, 0);
    {
        dim3 grid((EE + 255) / 256, MM);
        count_kernel<<<grid, 256, 0, s2>>>(dst);                // launch 5
    }
    {
        dim3 grid((NN + 127) / 128, HD / 128, MM);
        feat_mma_kernel<<<grid, 256, FEAT_SMEM_BYTES>>>(h, attn_l, attn_r);  // launch 6
    }
    scan_partial<<<dim3(NB, MM), 256, 0, s2>>>();
    scan_mid<<<MM, 128, 0, s2>>>();
    scan_final<<<dim3(NB, MM), 256, 0, s2>>>();
    {
        dim3 grid((EE + 255) / 256, MM);
        scatter_kernel<<<grid, 256, 0, s2>>>(src, dst);
    }
    cudaEventRecord(ev_join, s2);
    cudaStreamWaitEvent(0, ev_join, 0);

    {
        dim3 grid(NN, MM);
        agg_kernel<<<grid, 128>>>(bias_g);
    }
    sem_mma_kernel<<<(MM * NN) / 64, 256, SEM_SMEM_BYTES>>>(sem_b1, sem_W2);
    wsum_kernel<<<(MM * NN + 255) / 256, 256>>>();
    beta_kernel<<<1, 1>>>();
    pred_kernel<<<(NN * 32 + 255) / 256, 256>>>(pred_W, pred_b, out);
}

// round 8
// speedup vs baseline: 2.7431x; 1.0300x over previous
#include <cuda_runtime.h>
#include <cuda_bf16.h>
#include <cuda_fp16.h>
#include <cstdint>
#include <math.h>

// Problem constants
constexpr int NN   = 20000;
constexpr int EE   = 320000;
constexpr int FF   = 256;
constexpr int HH   = 8;
constexpr int DD   = 64;
constexpr int HD   = 512;
constexpr int MM   = 2;
constexpr int CC   = 5;
constexpr int HIDN = 128;
constexpr int NB   = 80;

// ---------------- device scratch ----------------
__device__ __half g_feat_h[MM][NN][HD];
__device__ __half g_z_h[MM][NN][HD];
__device__ float g_el[MM][NN][HH];
__device__ float g_er[MM][NN][HH];
__device__ int   g_deg[MM][NN];
__device__ int   g_rowptr[MM][NN + 1];
__device__ int   g_cur[MM][NN];
__device__ int   g_csr_src[MM][EE];
__device__ float g_w[MM * NN];
__device__ float g_wsum[MM];
__device__ float g_beta[MM];
__device__ int   g_psum[MM][NB];
__device__ int   g_boff[MM][NB];
__device__ __nv_bfloat16 g_Wt_hi[MM][HD][FF];
__device__ __nv_bfloat16 g_Wt_lo[MM][HD][FF];
__device__ __nv_bfloat16 g_W1t_hi[HIDN][HD];

// ---------------- helpers ----------------
__device__ __forceinline__ uint32_t pack_bf2(float x, float y) {
    __nv_bfloat162 p = __floats2bfloat162_rn(x, y);
    return *(uint32_t*)&p;
}
__device__ __forceinline__ float bf_res(float x) {
    return x - __bfloat162float(__float2bfloat16(x));
}
__device__ __forceinline__ void split8(float4 a, float4 b, uint4& hi, uint4& lo) {
    hi.x = pack_bf2(a.x, a.y); hi.y = pack_bf2(a.z, a.w);
    hi.z = pack_bf2(b.x, b.y); hi.w = pack_bf2(b.z, b.w);
    lo.x = pack_bf2(bf_res(a.x), bf_res(a.y));
    lo.y = pack_bf2(bf_res(a.z), bf_res(a.w));
    lo.z = pack_bf2(bf_res(b.x), bf_res(b.y));
    lo.w = pack_bf2(bf_res(b.z), bf_res(b.w));
}
__device__ __forceinline__ float fast_tanh(float x) {
    float e2 = __expf(2.f * x);
    return __fdividef(e2 - 1.f, e2 + 1.f);
}
#define MMA_BF16(d, a, b) \
    asm volatile( \
        "mma.sync.aligned.m16n8k16.row.col.f32.bf16.bf16.f32 " \
        "{%0,%1,%2,%3}, {%4,%5,%6,%7}, {%8,%9}, {%0,%1,%2,%3};" \
        : "+f"((d)[0]), "+f"((d)[1]), "+f"((d)[2]), "+f"((d)[3]) \
        : "r"((a)[0]), "r"((a)[1]), "r"((a)[2]), "r"((a)[3]), \
          "r"((b)[0]), "r"((b)[1]))
#define CP_ASYNC16(smem_u32, gptr) \
    asm volatile("cp.async.cg.shared.global [%0], [%1], 16;" \
        :: "r"(smem_u32), "l"(gptr) : "memory")
#define CP_COMMIT() asm volatile("cp.async.commit_group;" ::: "memory")
#define CP_WAIT0()  asm volatile("cp.async.wait_group 0;" ::: "memory")

// ---------------- weight conversion ----------------
__global__ void conv_w_kernel(const float* __restrict__ W) {
    __shared__ float tile[32][33];
    int mp = blockIdx.z;
    int n0 = blockIdx.x * 32, k0 = blockIdx.y * 32;
    int tx = threadIdx.x, ty = threadIdx.y;  // 32 x 8
#pragma unroll
    for (int j = 0; j < 4; j++)
        tile[ty + j * 8][tx] = W[mp * FF * HD + (k0 + ty + j * 8) * HD + n0 + tx];
    __syncthreads();
#pragma unroll
    for (int j = 0; j < 4; j++) {
        int n = n0 + ty + j * 8, k = k0 + tx;
        float x = tile[tx][ty + j * 8];
        g_Wt_hi[mp][n][k] = __float2bfloat16(x);
        g_Wt_lo[mp][n][k] = __float2bfloat16(bf_res(x));
    }
}

__global__ void conv_w1t_kernel(const float* __restrict__ W1) {
    __shared__ float tile[32][33];
    int n0 = blockIdx.x * 32, k0 = blockIdx.y * 32;
    int tx = threadIdx.x, ty = threadIdx.y;
#pragma unroll
    for (int j = 0; j < 4; j++)
        tile[ty + j * 8][tx] = W1[(k0 + ty + j * 8) * HIDN + n0 + tx];
    __syncthreads();
#pragma unroll
    for (int j = 0; j < 4; j++) {
        int n = n0 + ty + j * 8, k = k0 + tx;
        g_W1t_hi[n][k] = __float2bfloat16(tile[tx][ty + j * 8]);
    }
}

// ---------------- feat GEMM: 128x128 block, double-buffered pipeline --------
// Buffer layout (per buffer, stride 73728): Ah 0, Al 18432, Bh 36864, Bl 55296
constexpr int BUF_STRIDE = 73728;
constexpr int FEAT_SMEM_BYTES = 2 * BUF_STRIDE + 1024;

__global__ void __launch_bounds__(256, 1)
feat_mma_kernel(const float* __restrict__ h,
                const float* __restrict__ al, const float* __restrict__ ar) {
    extern __shared__ char smem[];
    float* s_al = (float*)(smem + 2 * BUF_STRIDE);
    float* s_ar = s_al + 128;
    uint32_t smem_u32;
    {
        asm("{ .reg .u64 t; cvta.to.shared.u64 t, %1; cvt.u32.u64 %0, t; }"
            : "=r"(smem_u32) : "l"(smem));
    }

    const int t = threadIdx.x, lane = t & 31, wid = t >> 5;
    const int wm = wid & 3, wn = wid >> 2;        // 4(m) x 2(n)
    const int rowBase = blockIdx.x * 128;
    const int colBase = blockIdx.y * 128;          // 2 heads
    const int mp      = blockIdx.z;

    if (t < 128) {
        s_al[t] = al[mp * HD + colBase + t];
        s_ar[t] = ar[mp * HD + colBase + t];
    }

    // per-thread staging coordinates (A: 4 iters, B: 4 iters)
    const int a_row = t >> 1;                  // 0..127 (2 threads/row)
    const int a_kq  = (t & 1) * 32;            // 0 or 32 (each does 8+8 at +0,+16?) -- see below
    // We keep the original indexing scheme per j to stay simple:
    // j in 0..3: idx = t + j*256; row = idx>>3 (0..127), kq = (idx&7)*8 (0..56)
    (void)a_row; (void)a_kq;

    float4 va[4], vb[4];

    auto ldg_A = [&](int kc) {
#pragma unroll
        for (int j = 0; j < 4; j++) {
            int idx = t + j * 256;
            int row = idx >> 3, kq = (idx & 7) * 8;
            int grow = rowBase + row;
            va[j] = make_float4(0.f, 0.f, 0.f, 0.f);
            vb[j] = va[j];
            if (grow < NN) {
                const float* hp = &h[grow * FF + kc * 64 + kq];
                va[j] = *(const float4*)hp;
                vb[j] = *(const float4*)(hp + 4);
            }
        }
    };
    auto sts_A = [&](int buf) {
        char* base = smem + buf * BUF_STRIDE;
#pragma unroll
        for (int j = 0; j < 4; j++) {
            int idx = t + j * 256;
            int row = idx >> 3, kq = (idx & 7) * 8;
            uint4 hi, lo;
            split8(va[j], vb[j], hi, lo);
            *(uint4*)(base + row * 144 + kq * 2) = hi;             // Ah
            *(uint4*)(base + 18432 + row * 144 + kq * 2) = lo;     // Al
        }
    };
    auto cp_B = [&](int kc, int buf) {
        uint32_t base = smem_u32 + buf * BUF_STRIDE;
#pragma unroll
        for (int j = 0; j < 4; j++) {
            int idx = t + j * 256;
            int row = idx >> 3, kq = (idx & 7) * 8;
            uint32_t off = row * 144 + kq * 2;
            CP_ASYNC16(base + 36864 + off, &g_Wt_hi[mp][colBase + row][kc * 64 + kq]);
            CP_ASYNC16(base + 55296 + off, &g_Wt_lo[mp][colBase + row][kc * 64 + kq]);
        }
    };

    float d[2][8][4] = {};

    // prologue: fill buffer 0 with chunk 0
    cp_B(0, 0);
    CP_COMMIT();
    ldg_A(0);
    sts_A(0);
    CP_WAIT0();
    __syncthreads();

    for (int kc = 0; kc < 4; kc++) {
        const int cur = kc & 1;
        if (kc < 3) {
            cp_B(kc + 1, cur ^ 1);
            CP_COMMIT();
            ldg_A(kc + 1);          // LDGs in flight during MMA loop below
        }

        const char* base = smem + cur * BUF_STRIDE;
        const __nv_bfloat16 (*Ah)[72] = (const __nv_bfloat16(*)[72])(base);
        const __nv_bfloat16 (*Al)[72] = (const __nv_bfloat16(*)[72])(base + 18432);
        const __nv_bfloat16 (*Bh)[72] = (const __nv_bfloat16(*)[72])(base + 36864);
        const __nv_bfloat16 (*Bl)[72] = (const __nv_bfloat16(*)[72])(base + 55296);

#pragma unroll
        for (int ks = 0; ks < 4; ks++) {
            const int kk = ks * 16 + (lane & 3) * 2;
            uint32_t ah[2][4], alr[2][4], bh[8][2], bl[8][2];
#pragma unroll
            for (int mi = 0; mi < 2; mi++) {
                int r = wm * 32 + mi * 16 + (lane >> 2);
                ah[mi][0] = *(const uint32_t*)&Ah[r][kk];
                ah[mi][1] = *(const uint32_t*)&Ah[r + 8][kk];
                ah[mi][2] = *(const uint32_t*)&Ah[r][kk + 8];
                ah[mi][3] = *(const uint32_t*)&Ah[r + 8][kk + 8];
                alr[mi][0] = *(const uint32_t*)&Al[r][kk];
                alr[mi][1] = *(const uint32_t*)&Al[r + 8][kk];
                alr[mi][2] = *(const uint32_t*)&Al[r][kk + 8];
                alr[mi][3] = *(const uint32_t*)&Al[r + 8][kk + 8];
            }
#pragma unroll
            for (int ni = 0; ni < 8; ni++) {
                int n = wn * 64 + ni * 8 + (lane >> 2);
                bh[ni][0] = *(const uint32_t*)&Bh[n][kk];
                bh[ni][1] = *(const uint32_t*)&Bh[n][kk + 8];
                bl[ni][0] = *(const uint32_t*)&Bl[n][kk];
                bl[ni][1] = *(const uint32_t*)&Bl[n][kk + 8];
            }
#pragma unroll
            for (int mi = 0; mi < 2; mi++)
#pragma unroll
                for (int ni = 0; ni < 8; ni++) {
                    MMA_BF16(d[mi][ni], ah[mi], bh[ni]);
                    MMA_BF16(d[mi][ni], ah[mi], bl[ni]);
                    MMA_BF16(d[mi][ni], alr[mi], bh[ni]);
                }
        }

        if (kc < 3) {
            sts_A(cur ^ 1);
            CP_WAIT0();
        }
        __syncthreads();
    }

    // ---- epilogue: each warp's 64 cols = one head; el/er reduce in-warp ----
    const int head = colBase / DD + wn;
#pragma unroll
    for (int mi = 0; mi < 2; mi++) {
#pragma unroll
        for (int half = 0; half < 2; half++) {
            int r = wm * 32 + mi * 16 + half * 8 + (lane >> 2);
            int grow = rowBase + r;
            float el = 0.f, er = 0.f;
#pragma unroll
            for (int ni = 0; ni < 8; ni++) {
                float v0 = d[mi][ni][half * 2 + 0];
                float v1 = d[mi][ni][half * 2 + 1];
                int c = wn * 64 + ni * 8 + (lane & 3) * 2;
                el += v0 * s_al[c] + v1 * s_al[c + 1];
                er += v0 * s_ar[c] + v1 * s_ar[c + 1];
                if (grow < NN) {
                    __half2 hv = __floats2half2_rn(v0, v1);
                    *(__half2*)&g_feat_h[mp][grow][colBase + c] = hv;
                }
            }
            el += __shfl_xor_sync(0xffffffffu, el, 1);
            el += __shfl_xor_sync(0xffffffffu, el, 2);
            er += __shfl_xor_sync(0xffffffffu, er, 1);
            er += __shfl_xor_sync(0xffffffffu, er, 2);
            if ((lane & 3) == 0 && grow < NN) {
                g_el[mp][grow][head] = el;
                g_er[mp][grow][head] = er;
            }
        }
    }
}

// ---------------- CSR build ----------------
__global__ void count_kernel(const int* __restrict__ dst) {
    int mp = blockIdx.y;
    int e = blockIdx.x * blockDim.x + threadIdx.x;
    if (e < EE) atomicAdd(&g_deg[mp][dst[mp * EE + e]], 1);
}

__global__ void scan_partial() {
    int mp = blockIdx.y;
    int i = blockIdx.x * 256 + threadIdx.x;
    int v = (i < NN) ? g_deg[mp][i] : 0;
#pragma unroll
    for (int off = 16; off; off >>= 1) v += __shfl_xor_sync(0xffffffffu, v, off);
    __shared__ int ws[8];
    if ((threadIdx.x & 31) == 0) ws[threadIdx.x >> 5] = v;
    __syncthreads();
    if (threadIdx.x == 0) {
        int s = 0;
#pragma unroll
        for (int w = 0; w < 8; w++) s += ws[w];
        g_psum[mp][blockIdx.x] = s;
    }
}

__global__ void scan_mid() {
    int mp = blockIdx.x;
    int t = threadIdx.x, lane = t & 31, wid = t >> 5;
    int v = (t < NB) ? g_psum[mp][t] : 0;
    int x = v;
#pragma unroll
    for (int off = 1; off < 32; off <<= 1) {
        int y = __shfl_up_sync(0xffffffffu, x, off);
        if (lane >= off) x += y;
    }
    __shared__ int ws[4];
    if (lane == 31) ws[wid] = x;
    __syncthreads();
    int woff = 0;
    for (int w = 0; w < wid; w++) woff += ws[w];
    if (t < NB) g_boff[mp][t] = woff + x - v;
}

__global__ void scan_final() {
    int mp = blockIdx.y;
    int t = threadIdx.x, lane = t & 31, wid = t >> 5;
    int i = blockIdx.x * 256 + t;
    int v = (i < NN) ? g_deg[mp][i] : 0;
    int x = v;
#pragma unroll
    for (int off = 1; off < 32; off <<= 1) {
        int y = __shfl_up_sync(0xffffffffu, x, off);
        if (lane >= off) x += y;
    }
    __shared__ int ws[8];
    if (lane == 31) ws[wid] = x;
    __syncthreads();
    int woff = 0;
    for (int w = 0; w < wid; w++) woff += ws[w];
    int excl = g_boff[mp][blockIdx.x] + woff + x - v;
    if (i < NN) {
        g_rowptr[mp][i] = excl;
        g_cur[mp][i]    = excl;
        if (i == NN - 1) g_rowptr[mp][NN] = excl + v;
    }
}

__global__ void scatter_kernel(const int* __restrict__ src,
                               const int* __restrict__ dst) {
    int mp = blockIdx.y;
    int e = blockIdx.x * blockDim.x + threadIdx.x;
    if (e < EE) {
        int d = dst[mp * EE + e];
        int pos = atomicAdd(&g_cur[mp][d], 1);
        g_csr_src[mp][pos] = src[mp * EE + e];
    }
}

// ---------------- edge softmax + aggregation (fp16 feat) --------------------
__global__ void agg_kernel(const float* __restrict__ bias) {
    const int v  = blockIdx.x;
    const int mp = blockIdx.y;
    const int t  = threadIdx.x;  // 128

    __shared__ float ser[HH], sden[HH];
    __shared__ float sex[16][HH];
    __shared__ int   ssrc[16];

    const int start = g_rowptr[mp][v];
    const int deg   = g_rowptr[mp][v + 1] - start;

    if (t < HH) {
        ser[t]  = g_er[mp][v][t];
        sden[t] = 0.f;
    }
    __syncthreads();

    float acc0 = 0.f, acc1 = 0.f, acc2 = 0.f, acc3 = 0.f;
    const int d0  = t * 4;
    const int myh = t >> 4;

    for (int base = 0; base < deg; base += 16) {
        int cn = min(16, deg - base);
        if (t < cn * 8) {
            int i = t >> 3, hh = t & 7;
            int s = g_csr_src[mp][start + base + i];
            if (hh == 0) ssrc[i] = s;
            float e = g_el[mp][s][hh] + ser[hh];
            e = (e > 0.f) ? e : 0.2f * e;
            sex[i][hh] = __expf(e);
        }
        __syncthreads();
        if (t < 8) {
            float dsum = 0.f;
            for (int i = 0; i < cn; i++) dsum += sex[i][t];
            sden[t] += dsum;
        }
#pragma unroll 4
        for (int i = 0; i < cn; i++) {
            int s = ssrc[i];
            float w = sex[i][myh];
            uint2 raw = *(const uint2*)&g_feat_h[mp][s][d0];
            float2 f01 = __half22float2(*(__half2*)&raw.x);
            float2 f23 = __half22float2(*(__half2*)&raw.y);
            acc0 += w * f01.x;
            acc1 += w * f01.y;
            acc2 += w * f23.x;
            acc3 += w * f23.y;
        }
        __syncthreads();
    }

    float inv = 1.f / fmaxf(sden[myh], 1e-9f);
    const float* b = bias + mp * HD + d0;
    float o0 = acc0 * inv + b[0];
    float o1 = acc1 * inv + b[1];
    float o2 = acc2 * inv + b[2];
    float o3 = acc3 * inv + b[3];
    o0 = (o0 > 0.f) ? o0 : (__expf(o0) - 1.f);
    o1 = (o1 > 0.f) ? o1 : (__expf(o1) - 1.f);
    o2 = (o2 > 0.f) ? o2 : (__expf(o2) - 1.f);
    o3 = (o3 > 0.f) ? o3 : (__expf(o3) - 1.f);
    uint2 zout;
    *(__half2*)&zout.x = __floats2half2_rn(o0, o1);
    *(__half2*)&zout.y = __floats2half2_rn(o2, o3);
    *(uint2*)&g_z_h[mp][v][d0] = zout;
}

// ---------------- semantic attention: single-product bf16 MMA ---------------
constexpr int SEM_SMEM_BYTES = 9216 + 18432 + 1280;

__global__ void __launch_bounds__(256)
sem_mma_kernel(const float* __restrict__ b1, const float* __restrict__ W2) {
    extern __shared__ char smem[];
    __nv_bfloat16 (*Ah)[72] = (__nv_bfloat16(*)[72])(smem);
    __nv_bfloat16 (*Bh)[72] = (__nv_bfloat16(*)[72])(smem + 9216);
    float* s_b1 = (float*)(smem + 27648);
    float* s_w2 = s_b1 + 128;
    float* s_wr = s_w2 + 128;

    const int t = threadIdx.x, lane = t & 31, wid = t >> 5;
    const int wm = wid & 1, wn = wid >> 1;
    const int rowBase = blockIdx.x * 64;
    const __half* Zh = &g_z_h[0][0][0];

    if (t < 128) { s_b1[t] = b1[t]; s_w2[t] = W2[t]; }
    if (t < 64) s_wr[t] = 0.f;

    float d[2][4][4] = {};

    for (int kc = 0; kc < 8; kc++) {
#pragma unroll
        for (int j = 0; j < 2; j++) {
            int idx = t + j * 256;
            int row = idx >> 3, kq = (idx & 7) * 8;
            uint4 raw = *(const uint4*)&Zh[(rowBase + row) * HD + kc * 64 + kq];
            float2 f0 = __half22float2(*(__half2*)&raw.x);
            float2 f1 = __half22float2(*(__half2*)&raw.y);
            float2 f2 = __half22float2(*(__half2*)&raw.z);
            float2 f3 = __half22float2(*(__half2*)&raw.w);
            uint4 hi;
            hi.x = pack_bf2(f0.x, f0.y); hi.y = pack_bf2(f1.x, f1.y);
            hi.z = pack_bf2(f2.x, f2.y); hi.w = pack_bf2(f3.x, f3.y);
            *(uint4*)&Ah[row][kq] = hi;
        }
#pragma unroll
        for (int j = 0; j < 4; j++) {
            int idx = t + j * 256;
            int row = idx >> 3, kq = (idx & 7) * 8;
            *(uint4*)&Bh[row][kq] = *(const uint4*)&g_W1t_hi[row][kc * 64 + kq];
        }
        __syncthreads();

#pragma unroll
        for (int ks = 0; ks < 4; ks++) {
            const int kk = ks * 16 + (lane & 3) * 2;
            uint32_t ah[2][4], bh[4][2];
#pragma unroll
            for (int mi = 0; mi < 2; mi++) {
                int r = wm * 32 + mi * 16 + (lane >> 2);
                ah[mi][0] = *(const uint32_t*)&Ah[r][kk];
                ah[mi][1] = *(const uint32_t*)&Ah[r + 8][kk];
                ah[mi][2] = *(const uint32_t*)&Ah[r][kk + 8];
                ah[mi][3] = *(const uint32_t*)&Ah[r + 8][kk + 8];
            }
#pragma unroll
            for (int ni = 0; ni < 4; ni++) {
                int n = wn * 32 + ni * 8 + (lane >> 2);
                bh[ni][0] = *(const uint32_t*)&Bh[n][kk];
                bh[ni][1] = *(const uint32_t*)&Bh[n][kk + 8];
            }
#pragma unroll
            for (int mi = 0; mi < 2; mi++)
#pragma unroll
                for (int ni = 0; ni < 4; ni++)
                    MMA_BF16(d[mi][ni], ah[mi], bh[ni]);
        }
        __syncthreads();
    }

#pragma unroll
    for (int mi = 0; mi < 2; mi++) {
#pragma unroll
        for (int half = 0; half < 2; half++) {
            float p = 0.f;
#pragma unroll
            for (int ni = 0; ni < 4; ni++) {
                int c = wn * 32 + ni * 8 + (lane & 3) * 2;
                p += fast_tanh(d[mi][ni][half * 2 + 0] + s_b1[c]) * s_w2[c];
                p += fast_tanh(d[mi][ni][half * 2 + 1] + s_b1[c + 1]) * s_w2[c + 1];
            }
            p += __shfl_xor_sync(0xffffffffu, p, 1);
            p += __shfl_xor_sync(0xffffffffu, p, 2);
            if ((lane & 3) == 0)
                atomicAdd(&s_wr[wm * 32 + mi * 16 + half * 8 + (lane >> 2)], p);
        }
    }
    __syncthreads();
    if (t < 64) g_w[rowBase + t] = s_wr[t];
}

__global__ void wsum_kernel() {
    __shared__ float sp[MM];
    if (threadIdx.x < MM) sp[threadIdx.x] = 0.f;
    __syncthreads();
    int i = blockIdx.x * blockDim.x + threadIdx.x;
    if (i < MM * NN) atomicAdd(&sp[i / NN], g_w[i]);
    __syncthreads();
    if (threadIdx.x < MM) atomicAdd(&g_wsum[threadIdx.x], sp[threadIdx.x]);
}

__global__ void beta_kernel() {
    float a = g_wsum[0] / (float)NN;
    float b = g_wsum[1] / (float)NN;
    float m = fmaxf(a, b);
    float ea = __expf(a - m), eb = __expf(b - m);
    float s = ea + eb;
    g_beta[0] = ea / s;
    g_beta[1] = eb / s;
}

__global__ void pred_kernel(const float* __restrict__ pw,
                            const float* __restrict__ pb,
                            float* __restrict__ out) {
    int gwarp = (blockIdx.x * blockDim.x + threadIdx.x) >> 5;
    int lane  = threadIdx.x & 31;
    if (gwarp >= NN) return;
    float b0 = g_beta[0], b1 = g_beta[1];
    float acc[CC];
#pragma unroll
    for (int c = 0; c < CC; c++) acc[c] = 0.f;
    const __half2* z0 = (const __half2*)g_z_h[0][gwarp];
    const __half2* z1 = (const __half2*)g_z_h[1][gwarp];
#pragma unroll
    for (int i = 0; i < HD / 64; i++) {
        int d2 = lane + i * 32;
        float2 f0 = __half22float2(z0[d2]);
        float2 f1 = __half22float2(z1[d2]);
        float hv0 = b0 * f0.x + b1 * f1.x;
        float hv1 = b0 * f0.y + b1 * f1.y;
        int dd = d2 * 2;
#pragma unroll
        for (int c = 0; c < CC; c++)
            acc[c] += hv0 * __ldg(&pw[dd * CC + c]) + hv1 * __ldg(&pw[(dd + 1) * CC + c]);
    }
#pragma unroll
    for (int off = 16; off; off >>= 1)
#pragma unroll
        for (int c = 0; c < CC; c++)
            acc[c] += __shfl_xor_sync(0xffffffffu, acc[c], off);
    if (lane == 0) {
#pragma unroll
        for (int c = 0; c < CC; c++) out[gwarp * CC + c] = acc[c] + pb[c];
    }
}

// ---------------- launch ----------------
extern "C" void kernel_launch(void* const* d_in, const int* in_sizes, int n_in,
                              void* d_out, int out_size) {
    const float* h      = (const float*)d_in[0];
    const int*   src    = (const int*)d_in[1];
    const int*   dst    = (const int*)d_in[2];
    const float* W      = (const float*)d_in[3];
    const float* attn_l = (const float*)d_in[4];
    const float* attn_r = (const float*)d_in[5];
    const float* bias_g = (const float*)d_in[6];
    const float* sem_W1 = (const float*)d_in[7];
    const float* sem_b1 = (const float*)d_in[8];
    const float* sem_W2 = (const float*)d_in[9];
    const float* pred_W = (const float*)d_in[10];
    const float* pred_b = (const float*)d_in[11];
    float* out = (float*)d_out;

    static cudaStream_t s2 = nullptr;
    static cudaEvent_t ev_fork = nullptr, ev_join = nullptr;
    if (s2 == nullptr) {
        cudaStreamCreateWithFlags(&s2, cudaStreamNonBlocking);
        cudaEventCreateWithFlags(&ev_fork, cudaEventDisableTiming);
        cudaEventCreateWithFlags(&ev_join, cudaEventDisableTiming);
    }

    cudaFuncSetAttribute(feat_mma_kernel,
                         cudaFuncAttributeMaxDynamicSharedMemorySize, FEAT_SMEM_BYTES);
    cudaFuncSetAttribute(sem_mma_kernel,
                         cudaFuncAttributeMaxDynamicSharedMemorySize, SEM_SMEM_BYTES);

    void* p_deg = nullptr;
    void* p_ws  = nullptr;
    cudaGetSymbolAddress(&p_deg, g_deg);
    cudaGetSymbolAddress(&p_ws, g_wsum);
    cudaMemsetAsync(p_deg, 0, sizeof(int) * MM * NN, 0);        // launch 1
    cudaMemsetAsync(p_ws, 0, sizeof(float) * MM, 0);            // launch 2

    {
        dim3 grid(HD / 32, FF / 32, MM);
        conv_w_kernel<<<grid, dim3(32, 8)>>>(W);                // launch 3
    }
    conv_w1t_kernel<<<dim3(HIDN / 32, HD / 32), dim3(32, 8)>>>(sem_W1);  // launch 4

    cudaEventRecord(ev_fork, 0);
    cudaStreamWaitEvent(s2, ev_fork, 0);
    {
        dim3 grid((EE + 255) / 256, MM);
        count_kernel<<<grid, 256, 0, s2>>>(dst);                // launch 5
    }
    {
        dim3 grid((NN + 127) / 128, HD / 128, MM);
        feat_mma_kernel<<<grid, 256, FEAT_SMEM_BYTES>>>(h, attn_l, attn_r);  // launch 6
    }
    scan_partial<<<dim3(NB, MM), 256, 0, s2>>>();
    scan_mid<<<MM, 128, 0, s2>>>();
    scan_final<<<dim3(NB, MM), 256, 0, s2>>>();
    {
        dim3 grid((EE + 255) / 256, MM);
        scatter_kernel<<<grid, 256, 0, s2>>>(src, dst);
    }
    cudaEventRecord(ev_join, s2);
    cudaStreamWaitEvent(0, ev_join, 0);

    {
        dim3 grid(NN, MM);
        agg_kernel<<<grid, 128>>>(bias_g);
    }
    sem_mma_kernel<<<(MM * NN) / 64, 256, SEM_SMEM_BYTES>>>(sem_b1, sem_W2);
    wsum_kernel<<<(MM * NN + 255) / 256, 256>>>();
    beta_kernel<<<1, 1>>>();
    pred_kernel<<<(NN * 32 + 255) / 256, 256>>>(pred_W, pred_b, out);
}

// round 9
// speedup vs baseline: 2.7828x; 1.0145x over previous
#include <cuda_runtime.h>
#include <cuda_bf16.h>
#include <cuda_fp16.h>
#include <cstdint>
#include <math.h>

// Problem constants
constexpr int NN   = 20000;
constexpr int EE   = 320000;
constexpr int FF   = 256;
constexpr int HH   = 8;
constexpr int DD   = 64;
constexpr int HD   = 512;
constexpr int MM   = 2;
constexpr int CC   = 5;
constexpr int HIDN = 128;
constexpr int NB   = 80;

// ---------------- device scratch ----------------
__device__ __half g_feat_h[MM][NN][HD];
__device__ __half g_z_h[MM][NN][HD];
__device__ float g_el[MM][NN][HH];
__device__ float g_er[MM][NN][HH];
__device__ int   g_deg[MM][NN];
__device__ int   g_rowptr[MM][NN + 1];
__device__ int   g_cur[MM][NN];
__device__ int   g_csr_src[MM][EE];
__device__ float g_w[MM * NN];
__device__ float g_wsum[MM];
__device__ float g_beta[MM];
__device__ int   g_psum[MM][NB];
__device__ int   g_boff[MM][NB];
__device__ __nv_bfloat16 g_Wt_hi[MM][HD][FF];
__device__ __nv_bfloat16 g_Wt_lo[MM][HD][FF];
__device__ __nv_bfloat16 g_W1t_hi[HIDN][HD];

// ---------------- helpers ----------------
__device__ __forceinline__ uint32_t pack_bf2(float x, float y) {
    __nv_bfloat162 p = __floats2bfloat162_rn(x, y);
    return *(uint32_t*)&p;
}
__device__ __forceinline__ float bf_res(float x) {
    return x - __bfloat162float(__float2bfloat16(x));
}
__device__ __forceinline__ void split8(float4 a, float4 b, uint4& hi, uint4& lo) {
    hi.x = pack_bf2(a.x, a.y); hi.y = pack_bf2(a.z, a.w);
    hi.z = pack_bf2(b.x, b.y); hi.w = pack_bf2(b.z, b.w);
    lo.x = pack_bf2(bf_res(a.x), bf_res(a.y));
    lo.y = pack_bf2(bf_res(a.z), bf_res(a.w));
    lo.z = pack_bf2(bf_res(b.x), bf_res(b.y));
    lo.w = pack_bf2(bf_res(b.z), bf_res(b.w));
}
__device__ __forceinline__ float fast_tanh(float x) {
    float e2 = __expf(2.f * x);
    return __fdividef(e2 - 1.f, e2 + 1.f);
}
#define MMA_BF16(d, a, b) \
    asm volatile( \
        "mma.sync.aligned.m16n8k16.row.col.f32.bf16.bf16.f32 " \
        "{%0,%1,%2,%3}, {%4,%5,%6,%7}, {%8,%9}, {%0,%1,%2,%3};" \
        : "+f"((d)[0]), "+f"((d)[1]), "+f"((d)[2]), "+f"((d)[3]) \
        : "r"((a)[0]), "r"((a)[1]), "r"((a)[2]), "r"((a)[3]), \
          "r"((b)[0]), "r"((b)[1]))
#define LDSM_X4(r, addr) \
    asm volatile("ldmatrix.sync.aligned.m8n8.x4.shared.b16 {%0,%1,%2,%3}, [%4];" \
        : "=r"((r)[0]), "=r"((r)[1]), "=r"((r)[2]), "=r"((r)[3]) : "r"(addr))
#define CP_ASYNC16(smem_u32, gptr) \
    asm volatile("cp.async.cg.shared.global [%0], [%1], 16;" \
        :: "r"(smem_u32), "l"(gptr) : "memory")
#define CP_COMMIT() asm volatile("cp.async.commit_group;" ::: "memory")
#define CP_WAIT0()  asm volatile("cp.async.wait_group 0;" ::: "memory")

// ---------------- weight conversion ----------------
__global__ void conv_w_kernel(const float* __restrict__ W) {
    __shared__ float tile[32][33];
    int mp = blockIdx.z;
    int n0 = blockIdx.x * 32, k0 = blockIdx.y * 32;
    int tx = threadIdx.x, ty = threadIdx.y;  // 32 x 8
#pragma unroll
    for (int j = 0; j < 4; j++)
        tile[ty + j * 8][tx] = W[mp * FF * HD + (k0 + ty + j * 8) * HD + n0 + tx];
    __syncthreads();
#pragma unroll
    for (int j = 0; j < 4; j++) {
        int n = n0 + ty + j * 8, k = k0 + tx;
        float x = tile[tx][ty + j * 8];
        g_Wt_hi[mp][n][k] = __float2bfloat16(x);
        g_Wt_lo[mp][n][k] = __float2bfloat16(bf_res(x));
    }
}

__global__ void conv_w1t_kernel(const float* __restrict__ W1) {
    __shared__ float tile[32][33];
    int n0 = blockIdx.x * 32, k0 = blockIdx.y * 32;
    int tx = threadIdx.x, ty = threadIdx.y;
#pragma unroll
    for (int j = 0; j < 4; j++)
        tile[ty + j * 8][tx] = W1[(k0 + ty + j * 8) * HIDN + n0 + tx];
    __syncthreads();
#pragma unroll
    for (int j = 0; j < 4; j++) {
        int n = n0 + ty + j * 8, k = k0 + tx;
        g_W1t_hi[n][k] = __float2bfloat16(tile[tx][ty + j * 8]);
    }
}

// ---------------- feat GEMM: 128x128 block, pipelined, LDSM fragments -------
// Buffer layout (stride 73728): Ah 0, Al 18432, Bh 36864, Bl 55296; row 144 B
constexpr int BUF_STRIDE = 73728;
constexpr int FEAT_SMEM_BYTES = 2 * BUF_STRIDE + 1024;

__global__ void __launch_bounds__(256, 1)
feat_mma_kernel(const float* __restrict__ h,
                const float* __restrict__ al, const float* __restrict__ ar) {
    extern __shared__ char smem[];
    float* s_al = (float*)(smem + 2 * BUF_STRIDE);
    float* s_ar = s_al + 128;
    uint32_t smem_u32;
    asm("{ .reg .u64 t; cvta.to.shared.u64 t, %1; cvt.u32.u64 %0, t; }"
        : "=r"(smem_u32) : "l"(smem));

    const int t = threadIdx.x, lane = t & 31, wid = t >> 5;
    const int wm = wid & 3, wn = wid >> 2;        // 4(m) x 2(n)
    const int rowBase = blockIdx.x * 128;
    const int colBase = blockIdx.y * 128;          // 2 heads
    const int mp      = blockIdx.z;

    if (t < 128) {
        s_al[t] = al[mp * HD + colBase + t];
        s_ar[t] = ar[mp * HD + colBase + t];
    }

    // LDSM lane-address components (offset within a buffer)
    const int l_in  = lane & 7;         // row within 8x8 tile
    const int l_t01 = (lane >> 3) & 1;  // +8 rows for tiles 1,3
    const int l_t23 = lane >> 4;        // +8 k-cols (16 bytes) for tiles 2,3
    // A (mi tiles at rows wm*32 + mi*16): tiles (r, r+8, r|k+8, r+8|k+8)
    const uint32_t a_off0 = (uint32_t)(wm * 32 + l_in + l_t01 * 8) * 144 + l_t23 * 16;
    // B pair p covers ni=2p,2p+1: tiles (n, n|k+8, n+8, n+8|k+8)
    const uint32_t b_off0 = (uint32_t)(wn * 64 + l_in + (lane >> 4) * 8) * 144
                          + ((lane >> 3) & 1) * 16;

    float4 va[4], vb[4];

    auto ldg_A = [&](int kc) {
#pragma unroll
        for (int j = 0; j < 4; j++) {
            int idx = t + j * 256;
            int row = idx >> 3, kq = (idx & 7) * 8;
            int grow = rowBase + row;
            va[j] = make_float4(0.f, 0.f, 0.f, 0.f);
            vb[j] = va[j];
            if (grow < NN) {
                const float* hp = &h[grow * FF + kc * 64 + kq];
                va[j] = *(const float4*)hp;
                vb[j] = *(const float4*)(hp + 4);
            }
        }
    };
    auto sts_A = [&](int buf) {
        char* base = smem + buf * BUF_STRIDE;
#pragma unroll
        for (int j = 0; j < 4; j++) {
            int idx = t + j * 256;
            int row = idx >> 3, kq = (idx & 7) * 8;
            uint4 hi, lo;
            split8(va[j], vb[j], hi, lo);
            *(uint4*)(base + row * 144 + kq * 2) = hi;             // Ah
            *(uint4*)(base + 18432 + row * 144 + kq * 2) = lo;     // Al
        }
    };
    auto cp_B = [&](int kc, int buf) {
        uint32_t base = smem_u32 + buf * BUF_STRIDE;
#pragma unroll
        for (int j = 0; j < 4; j++) {
            int idx = t + j * 256;
            int row = idx >> 3, kq = (idx & 7) * 8;
            uint32_t off = row * 144 + kq * 2;
            CP_ASYNC16(base + 36864 + off, &g_Wt_hi[mp][colBase + row][kc * 64 + kq]);
            CP_ASYNC16(base + 55296 + off, &g_Wt_lo[mp][colBase + row][kc * 64 + kq]);
        }
    };

    float d[2][8][4] = {};

    cp_B(0, 0);
    CP_COMMIT();
    ldg_A(0);
    sts_A(0);
    CP_WAIT0();
    __syncthreads();

    for (int kc = 0; kc < 4; kc++) {
        const int cur = kc & 1;
        if (kc < 3) {
            cp_B(kc + 1, cur ^ 1);
            CP_COMMIT();
            ldg_A(kc + 1);
        }

        const uint32_t bufb = smem_u32 + cur * BUF_STRIDE;

#pragma unroll
        for (int ks = 0; ks < 4; ks++) {
            const uint32_t kb = (uint32_t)ks * 32;
            uint32_t ah[2][4], alr[2][4], bf[4][4];  // bf[p] = {b2p0,b2p1,b2p+1 0,b2p+1 1}
#pragma unroll
            for (int mi = 0; mi < 2; mi++) {
                uint32_t ao = bufb + a_off0 + (uint32_t)(mi * 16) * 144 + kb;
                LDSM_X4(ah[mi], ao);
                LDSM_X4(alr[mi], ao + 18432);
            }
            uint32_t bh_r[4][4], bl_r[4][4];
#pragma unroll
            for (int p = 0; p < 4; p++) {
                uint32_t bo = bufb + 36864 + b_off0 + (uint32_t)(p * 16) * 144 + kb;
                LDSM_X4(bh_r[p], bo);
                LDSM_X4(bl_r[p], bo + 18432);
            }
            (void)bf;
#pragma unroll
            for (int mi = 0; mi < 2; mi++)
#pragma unroll
                for (int p = 0; p < 4; p++) {
#pragma unroll
                    for (int q = 0; q < 2; q++) {
                        int ni = p * 2 + q;
                        uint32_t bhq[2] = { bh_r[p][q * 2], bh_r[p][q * 2 + 1] };
                        uint32_t blq[2] = { bl_r[p][q * 2], bl_r[p][q * 2 + 1] };
                        MMA_BF16(d[mi][ni], ah[mi], bhq);
                        MMA_BF16(d[mi][ni], ah[mi], blq);
                        MMA_BF16(d[mi][ni], alr[mi], bhq);
                    }
                }
        }

        if (kc < 3) {
            sts_A(cur ^ 1);
            CP_WAIT0();
        }
        __syncthreads();
    }

    // ---- epilogue: each warp's 64 cols = one head; el/er reduce in-warp ----
    const int head = colBase / DD + wn;
#pragma unroll
    for (int mi = 0; mi < 2; mi++) {
#pragma unroll
        for (int half = 0; half < 2; half++) {
            int r = wm * 32 + mi * 16 + half * 8 + (lane >> 2);
            int grow = rowBase + r;
            float el = 0.f, er = 0.f;
#pragma unroll
            for (int ni = 0; ni < 8; ni++) {
                float v0 = d[mi][ni][half * 2 + 0];
                float v1 = d[mi][ni][half * 2 + 1];
                int c = wn * 64 + ni * 8 + (lane & 3) * 2;
                el += v0 * s_al[c] + v1 * s_al[c + 1];
                er += v0 * s_ar[c] + v1 * s_ar[c + 1];
                if (grow < NN) {
                    __half2 hv = __floats2half2_rn(v0, v1);
                    *(__half2*)&g_feat_h[mp][grow][colBase + c] = hv;
                }
            }
            el += __shfl_xor_sync(0xffffffffu, el, 1);
            el += __shfl_xor_sync(0xffffffffu, el, 2);
            er += __shfl_xor_sync(0xffffffffu, er, 1);
            er += __shfl_xor_sync(0xffffffffu, er, 2);
            if ((lane & 3) == 0 && grow < NN) {
                g_el[mp][grow][head] = el;
                g_er[mp][grow][head] = er;
            }
        }
    }
}

// ---------------- CSR build ----------------
__global__ void count_kernel(const int* __restrict__ dst) {
    int mp = blockIdx.y;
    int e = blockIdx.x * blockDim.x + threadIdx.x;
    if (e < EE) atomicAdd(&g_deg[mp][dst[mp * EE + e]], 1);
}

__global__ void scan_partial() {
    int mp = blockIdx.y;
    int i = blockIdx.x * 256 + threadIdx.x;
    int v = (i < NN) ? g_deg[mp][i] : 0;
#pragma unroll
    for (int off = 16; off; off >>= 1) v += __shfl_xor_sync(0xffffffffu, v, off);
    __shared__ int ws[8];
    if ((threadIdx.x & 31) == 0) ws[threadIdx.x >> 5] = v;
    __syncthreads();
    if (threadIdx.x == 0) {
        int s = 0;
#pragma unroll
        for (int w = 0; w < 8; w++) s += ws[w];
        g_psum[mp][blockIdx.x] = s;
    }
}

__global__ void scan_mid() {
    int mp = blockIdx.x;
    int t = threadIdx.x, lane = t & 31, wid = t >> 5;
    int v = (t < NB) ? g_psum[mp][t] : 0;
    int x = v;
#pragma unroll
    for (int off = 1; off < 32; off <<= 1) {
        int y = __shfl_up_sync(0xffffffffu, x, off);
        if (lane >= off) x += y;
    }
    __shared__ int ws[4];
    if (lane == 31) ws[wid] = x;
    __syncthreads();
    int woff = 0;
    for (int w = 0; w < wid; w++) woff += ws[w];
    if (t < NB) g_boff[mp][t] = woff + x - v;
}

__global__ void scan_final() {
    int mp = blockIdx.y;
    int t = threadIdx.x, lane = t & 31, wid = t >> 5;
    int i = blockIdx.x * 256 + t;
    int v = (i < NN) ? g_deg[mp][i] : 0;
    int x = v;
#pragma unroll
    for (int off = 1; off < 32; off <<= 1) {
        int y = __shfl_up_sync(0xffffffffu, x, off);
        if (lane >= off) x += y;
    }
    __shared__ int ws[8];
    if (lane == 31) ws[wid] = x;
    __syncthreads();
    int woff = 0;
    for (int w = 0; w < wid; w++) woff += ws[w];
    int excl = g_boff[mp][blockIdx.x] + woff + x - v;
    if (i < NN) {
        g_rowptr[mp][i] = excl;
        g_cur[mp][i]    = excl;
        if (i == NN - 1) g_rowptr[mp][NN] = excl + v;
    }
}

__global__ void scatter_kernel(const int* __restrict__ src,
                               const int* __restrict__ dst) {
    int mp = blockIdx.y;
    int e = blockIdx.x * blockDim.x + threadIdx.x;
    if (e < EE) {
        int d = dst[mp * EE + e];
        int pos = atomicAdd(&g_cur[mp][d], 1);
        g_csr_src[mp][pos] = src[mp * EE + e];
    }
}

// ---------------- edge softmax + aggregation (fp16 feat) --------------------
__global__ void agg_kernel(const float* __restrict__ bias) {
    const int v  = blockIdx.x;
    const int mp = blockIdx.y;
    const int t  = threadIdx.x;  // 128

    __shared__ float ser[HH], sden[HH];
    __shared__ float sex[16][HH];
    __shared__ int   ssrc[16];

    const int start = g_rowptr[mp][v];
    const int deg   = g_rowptr[mp][v + 1] - start;

    if (t < HH) {
        ser[t]  = g_er[mp][v][t];
        sden[t] = 0.f;
    }
    __syncthreads();

    float acc0 = 0.f, acc1 = 0.f, acc2 = 0.f, acc3 = 0.f;
    const int d0  = t * 4;
    const int myh = t >> 4;

    for (int base = 0; base < deg; base += 16) {
        int cn = min(16, deg - base);
        if (t < cn * 8) {
            int i = t >> 3, hh = t & 7;
            int s = g_csr_src[mp][start + base + i];
            if (hh == 0) ssrc[i] = s;
            float e = g_el[mp][s][hh] + ser[hh];
            e = (e > 0.f) ? e : 0.2f * e;
            sex[i][hh] = __expf(e);
        }
        __syncthreads();
        if (t < 8) {
            float dsum = 0.f;
            for (int i = 0; i < cn; i++) dsum += sex[i][t];
            sden[t] += dsum;
        }
#pragma unroll 4
        for (int i = 0; i < cn; i++) {
            int s = ssrc[i];
            float w = sex[i][myh];
            uint2 raw = *(const uint2*)&g_feat_h[mp][s][d0];
            float2 f01 = __half22float2(*(__half2*)&raw.x);
            float2 f23 = __half22float2(*(__half2*)&raw.y);
            acc0 += w * f01.x;
            acc1 += w * f01.y;
            acc2 += w * f23.x;
            acc3 += w * f23.y;
        }
        __syncthreads();
    }

    float inv = 1.f / fmaxf(sden[myh], 1e-9f);
    const float* b = bias + mp * HD + d0;
    float o0 = acc0 * inv + b[0];
    float o1 = acc1 * inv + b[1];
    float o2 = acc2 * inv + b[2];
    float o3 = acc3 * inv + b[3];
    o0 = (o0 > 0.f) ? o0 : (__expf(o0) - 1.f);
    o1 = (o1 > 0.f) ? o1 : (__expf(o1) - 1.f);
    o2 = (o2 > 0.f) ? o2 : (__expf(o2) - 1.f);
    o3 = (o3 > 0.f) ? o3 : (__expf(o3) - 1.f);
    uint2 zout;
    *(__half2*)&zout.x = __floats2half2_rn(o0, o1);
    *(__half2*)&zout.y = __floats2half2_rn(o2, o3);
    *(uint2*)&g_z_h[mp][v][d0] = zout;
}

// ---------------- semantic attention: single-product bf16 MMA ---------------
constexpr int SEM_SMEM_BYTES = 9216 + 18432 + 1280;

__global__ void __launch_bounds__(256)
sem_mma_kernel(const float* __restrict__ b1, const float* __restrict__ W2) {
    extern __shared__ char smem[];
    __nv_bfloat16 (*Ah)[72] = (__nv_bfloat16(*)[72])(smem);
    __nv_bfloat16 (*Bh)[72] = (__nv_bfloat16(*)[72])(smem + 9216);
    float* s_b1 = (float*)(smem + 27648);
    float* s_w2 = s_b1 + 128;
    float* s_wr = s_w2 + 128;

    const int t = threadIdx.x, lane = t & 31, wid = t >> 5;
    const int wm = wid & 1, wn = wid >> 1;
    const int rowBase = blockIdx.x * 64;
    const __half* Zh = &g_z_h[0][0][0];

    if (t < 128) { s_b1[t] = b1[t]; s_w2[t] = W2[t]; }
    if (t < 64) s_wr[t] = 0.f;

    float d[2][4][4] = {};

    for (int kc = 0; kc < 8; kc++) {
#pragma unroll
        for (int j = 0; j < 2; j++) {
            int idx = t + j * 256;
            int row = idx >> 3, kq = (idx & 7) * 8;
            uint4 raw = *(const uint4*)&Zh[(rowBase + row) * HD + kc * 64 + kq];
            float2 f0 = __half22float2(*(__half2*)&raw.x);
            float2 f1 = __half22float2(*(__half2*)&raw.y);
            float2 f2 = __half22float2(*(__half2*)&raw.z);
            float2 f3 = __half22float2(*(__half2*)&raw.w);
            uint4 hi;
            hi.x = pack_bf2(f0.x, f0.y); hi.y = pack_bf2(f1.x, f1.y);
            hi.z = pack_bf2(f2.x, f2.y); hi.w = pack_bf2(f3.x, f3.y);
            *(uint4*)&Ah[row][kq] = hi;
        }
#pragma unroll
        for (int j = 0; j < 4; j++) {
            int idx = t + j * 256;
            int row = idx >> 3, kq = (idx & 7) * 8;
            *(uint4*)&Bh[row][kq] = *(const uint4*)&g_W1t_hi[row][kc * 64 + kq];
        }
        __syncthreads();

#pragma unroll
        for (int ks = 0; ks < 4; ks++) {
            const int kk = ks * 16 + (lane & 3) * 2;
            uint32_t ah[2][4], bh[4][2];
#pragma unroll
            for (int mi = 0; mi < 2; mi++) {
                int r = wm * 32 + mi * 16 + (lane >> 2);
                ah[mi][0] = *(const uint32_t*)&Ah[r][kk];
                ah[mi][1] = *(const uint32_t*)&Ah[r + 8][kk];
                ah[mi][2] = *(const uint32_t*)&Ah[r][kk + 8];
                ah[mi][3] = *(const uint32_t*)&Ah[r + 8][kk + 8];
            }
#pragma unroll
            for (int ni = 0; ni < 4; ni++) {
                int n = wn * 32 + ni * 8 + (lane >> 2);
                bh[ni][0] = *(const uint32_t*)&Bh[n][kk];
                bh[ni][1] = *(const uint32_t*)&Bh[n][kk + 8];
            }
#pragma unroll
            for (int mi = 0; mi < 2; mi++)
#pragma unroll
                for (int ni = 0; ni < 4; ni++)
                    MMA_BF16(d[mi][ni], ah[mi], bh[ni]);
        }
        __syncthreads();
    }

#pragma unroll
    for (int mi = 0; mi < 2; mi++) {
#pragma unroll
        for (int half = 0; half < 2; half++) {
            float p = 0.f;
#pragma unroll
            for (int ni = 0; ni < 4; ni++) {
                int c = wn * 32 + ni * 8 + (lane & 3) * 2;
                p += fast_tanh(d[mi][ni][half * 2 + 0] + s_b1[c]) * s_w2[c];
                p += fast_tanh(d[mi][ni][half * 2 + 1] + s_b1[c + 1]) * s_w2[c + 1];
            }
            p += __shfl_xor_sync(0xffffffffu, p, 1);
            p += __shfl_xor_sync(0xffffffffu, p, 2);
            if ((lane & 3) == 0)
                atomicAdd(&s_wr[wm * 32 + mi * 16 + half * 8 + (lane >> 2)], p);
        }
    }
    __syncthreads();
    if (t < 64) g_w[rowBase + t] = s_wr[t];
}

__global__ void wsum_kernel() {
    __shared__ float sp[MM];
    if (threadIdx.x < MM) sp[threadIdx.x] = 0.f;
    __syncthreads();
    int i = blockIdx.x * blockDim.x + threadIdx.x;
    if (i < MM * NN) atomicAdd(&sp[i / NN], g_w[i]);
    __syncthreads();
    if (threadIdx.x < MM) atomicAdd(&g_wsum[threadIdx.x], sp[threadIdx.x]);
}

__global__ void beta_kernel() {
    float a = g_wsum[0] / (float)NN;
    float b = g_wsum[1] / (float)NN;
    float m = fmaxf(a, b);
    float ea = __expf(a - m), eb = __expf(b - m);
    float s = ea + eb;
    g_beta[0] = ea / s;
    g_beta[1] = eb / s;
}

__global__ void pred_kernel(const float* __restrict__ pw,
                            const float* __restrict__ pb,
                            float* __restrict__ out) {
    int gwarp = (blockIdx.x * blockDim.x + threadIdx.x) >> 5;
    int lane  = threadIdx.x & 31;
    if (gwarp >= NN) return;
    float b0 = g_beta[0], b1 = g_beta[1];
    float acc[CC];
#pragma unroll
    for (int c = 0; c < CC; c++) acc[c] = 0.f;
    const __half2* z0 = (const __half2*)g_z_h[0][gwarp];
    const __half2* z1 = (const __half2*)g_z_h[1][gwarp];
#pragma unroll
    for (int i = 0; i < HD / 64; i++) {
        int d2 = lane + i * 32;
        float2 f0 = __half22float2(z0[d2]);
        float2 f1 = __half22float2(z1[d2]);
        float hv0 = b0 * f0.x + b1 * f1.x;
        float hv1 = b0 * f0.y + b1 * f1.y;
        int dd = d2 * 2;
#pragma unroll
        for (int c = 0; c < CC; c++)
            acc[c] += hv0 * __ldg(&pw[dd * CC + c]) + hv1 * __ldg(&pw[(dd + 1) * CC + c]);
    }
#pragma unroll
    for (int off = 16; off; off >>= 1)
#pragma unroll
        for (int c = 0; c < CC; c++)
            acc[c] += __shfl_xor_sync(0xffffffffu, acc[c], off);
    if (lane == 0) {
#pragma unroll
        for (int c = 0; c < CC; c++) out[gwarp * CC + c] = acc[c] + pb[c];
    }
}

// ---------------- launch ----------------
extern "C" void kernel_launch(void* const* d_in, const int* in_sizes, int n_in,
                              void* d_out, int out_size) {
    const float* h      = (const float*)d_in[0];
    const int*   src    = (const int*)d_in[1];
    const int*   dst    = (const int*)d_in[2];
    const float* W      = (const float*)d_in[3];
    const float* attn_l = (const float*)d_in[4];
    const float* attn_r = (const float*)d_in[5];
    const float* bias_g = (const float*)d_in[6];
    const float* sem_W1 = (const float*)d_in[7];
    const float* sem_b1 = (const float*)d_in[8];
    const float* sem_W2 = (const float*)d_in[9];
    const float* pred_W = (const float*)d_in[10];
    const float* pred_b = (const float*)d_in[11];
    float* out = (float*)d_out;

    static cudaStream_t s2 = nullptr;
    static cudaEvent_t ev_fork = nullptr, ev_join = nullptr;
    if (s2 == nullptr) {
        cudaStreamCreateWithFlags(&s2, cudaStreamNonBlocking);
        cudaEventCreateWithFlags(&ev_fork, cudaEventDisableTiming);
        cudaEventCreateWithFlags(&ev_join, cudaEventDisableTiming);
    }

    cudaFuncSetAttribute(feat_mma_kernel,
                         cudaFuncAttributeMaxDynamicSharedMemorySize, FEAT_SMEM_BYTES);
    cudaFuncSetAttribute(sem_mma_kernel,
                         cudaFuncAttributeMaxDynamicSharedMemorySize, SEM_SMEM_BYTES);

    void* p_deg = nullptr;
    void* p_ws  = nullptr;
    cudaGetSymbolAddress(&p_deg, g_deg);
    cudaGetSymbolAddress(&p_ws, g_wsum);
    cudaMemsetAsync(p_deg, 0, sizeof(int) * MM * NN, 0);        // launch 1
    cudaMemsetAsync(p_ws, 0, sizeof(float) * MM, 0);            // launch 2

    {
        dim3 grid(HD / 32, FF / 32, MM);
        conv_w_kernel<<<grid, dim3(32, 8)>>>(W);                // launch 3
    }
    conv_w1t_kernel<<<dim3(HIDN / 32, HD / 32), dim3(32, 8)>>>(sem_W1);  // launch 4

    cudaEventRecord(ev_fork, 0);
    cudaStreamWaitEvent(s2, ev_fork, 0);
    {
        dim3 grid((EE + 255) / 256, MM);
        count_kernel<<<grid, 256, 0, s2>>>(dst);                // launch 5
    }
    {
        dim3 grid((NN + 127) / 128, HD / 128, MM);
        feat_mma_kernel<<<grid, 256, FEAT_SMEM_BYTES>>>(h, attn_l, attn_r);  // launch 6
    }
    scan_partial<<<dim3(NB, MM), 256, 0, s2>>>();
    scan_mid<<<MM, 128, 0, s2>>>();
    scan_final<<<dim3(NB, MM), 256, 0, s2>>>();
    {
        dim3 grid((EE + 255) / 256, MM);
        scatter_kernel<<<grid, 256, 0, s2>>>(src, dst);
    }
    cudaEventRecord(ev_join, s2);
    cudaStreamWaitEvent(0, ev_join, 0);

    {
        dim3 grid(NN, MM);
        agg_kernel<<<grid, 128>>>(bias_g);
    }
    sem_mma_kernel<<<(MM * NN) / 64, 256, SEM_SMEM_BYTES>>>(sem_b1, sem_W2);
    wsum_kernel<<<(MM * NN + 255) / 256, 256>>>();
    beta_kernel<<<1, 1>>>();
    pred_kernel<<<(NN * 32 + 255) / 256, 256>>>(pred_W, pred_b, out);
}